// round 13
// baseline (speedup 1.0000x reference)
#include <cuda_runtime.h>
#include <cuda_bf16.h>
#include <math.h>
#include <stdint.h>

// ---------------- problem constants ----------------
#define BATCH 4
#define PP    196
#define FF    8
#define CC    768
#define NN    1569          // 1 + F*P
#define SS    1568          // F*P
#define HH    12
#define DD    64
#define SCALE 0.125f        // d^-0.5

#define M_QKV   (BATCH*NN)          // 6276
#define N_QKV   (3*CC)              // 2304
#define M_S     (BATCH*SS)          // 6272
#define OUT_ELEMS ((size_t)BATCH*NN*CC)   // 4,819,968

// ---------------- scratch ----------------
__device__ float g_qkv[(size_t)M_QKV * N_QKV];        // (B,N,3C) tf32-rounded
__device__ float g_xt [(size_t)M_S * FF * CC];        // (B,S,F,C)
__device__ float g_xd [(size_t)M_S * CC];             // x_diag, tf32-rounded
__device__ float g_q2 [(size_t)M_S * CC];             // tf32-rounded
__device__ float g_G  [(size_t)M_S * HH * CC];        // (B,S,h,C)
__device__ float g_pre[(size_t)M_QKV * CC];           // pre-proj, tf32-rounded
// tf32-rounded input copies
__device__ float g_xr    [(size_t)M_QKV * CC];
__device__ float g_wqkvr [(size_t)CC * 3 * CC];
__device__ float g_wqr   [(size_t)CC * CC];
__device__ float g_wkvr  [(size_t)CC * 2 * CC];
__device__ float g_wprojr[(size_t)CC * CC];

// ---------------- helpers ----------------
__device__ __forceinline__ float f2tf(float x) {
    uint32_t u;
    asm("cvt.rna.tf32.f32 %0, %1;" : "=r"(u) : "f"(x));
    return __uint_as_float(u);
}

__device__ __forceinline__ void mma_tf32(float* c, const uint32_t* a, const uint32_t* b) {
    asm volatile("mma.sync.aligned.m16n8k8.row.col.f32.tf32.tf32.f32 "
        "{%0,%1,%2,%3}, {%4,%5,%6,%7}, {%8,%9}, {%0,%1,%2,%3};"
        : "+f"(c[0]), "+f"(c[1]), "+f"(c[2]), "+f"(c[3])
        : "r"(a[0]), "r"(a[1]), "r"(a[2]), "r"(a[3]), "r"(b[0]), "r"(b[1]));
}

__device__ __forceinline__ void ldsm_x4(uint32_t* r, uint32_t saddr) {
    asm volatile("ldmatrix.sync.aligned.m8n8.x4.shared.b16 {%0,%1,%2,%3}, [%4];"
        : "=r"(r[0]), "=r"(r[1]), "=r"(r[2]), "=r"(r[3]) : "r"(saddr));
}

__device__ __forceinline__ void ldsm_x2(uint32_t* r, uint32_t saddr) {
    asm volatile("ldmatrix.sync.aligned.m8n8.x2.shared.b16 {%0,%1}, [%2];"
        : "=r"(r[0]), "=r"(r[1]) : "r"(saddr));
}

__device__ __forceinline__ uint32_t smem_u32(const void* p) {
    return (uint32_t)__cvta_generic_to_shared(p);
}

__device__ __forceinline__ void cp_async16(uint32_t saddr, const void* gptr, int src_bytes) {
    asm volatile("cp.async.cg.shared.global [%0], [%1], 16, %2;\n"
                 :: "r"(saddr), "l"(gptr), "r"(src_bytes));
}
#define CP_COMMIT() asm volatile("cp.async.commit_group;\n" ::: "memory")
#define CP_WAIT(n)  asm volatile("cp.async.wait_group %0;\n" :: "n"(n) : "memory")

// =============================================================
// round_all: tf32-round all 5 GEMM inputs in ONE launch.
// =============================================================
#define RC_N0 1204992
#define RC_N1 442368
#define RC_N2 147456
#define RC_N3 294912
#define RC_N4 147456
#define RC_TOTAL (RC_N0+RC_N1+RC_N2+RC_N3+RC_N4)

__global__ __launch_bounds__(256)
void round_all(const float* __restrict__ s0, float* __restrict__ d0,
               const float* __restrict__ s1, float* __restrict__ d1,
               const float* __restrict__ s2, float* __restrict__ d2,
               const float* __restrict__ s3, float* __restrict__ d3,
               const float* __restrict__ s4, float* __restrict__ d4)
{
    int i = blockIdx.x * 256 + threadIdx.x;
    if (i >= RC_TOTAL) return;
    const float4* src; float4* dst; int off = i;
    if (off < RC_N0)                { src = (const float4*)s0; dst = (float4*)d0; }
    else if ((off -= RC_N0) < RC_N1){ src = (const float4*)s1; dst = (float4*)d1; }
    else if ((off -= RC_N1) < RC_N2){ src = (const float4*)s2; dst = (float4*)d2; }
    else if ((off -= RC_N2) < RC_N3){ src = (const float4*)s3; dst = (float4*)d3; }
    else                            { off -= RC_N3; src = (const float4*)s4; dst = (float4*)d4; }
    float4 v = src[off];
    v.x = f2tf(v.x); v.y = f2tf(v.y); v.z = f2tf(v.z); v.w = f2tf(v.w);
    dst[off] = v;
}

// =============================================================
// TF32 GEMM v3: cp.async 3-stage pipeline, 128x128x16, 2 CTAs/SM.
// =============================================================
#define ALD3 20
#define BLD3 136
#define A_ST (128 * ALD3)
#define B_ST (16 * BLD3)
#define GT_SMEM ((3 * A_ST + 3 * B_ST) * 4)

template<bool HAS_BIAS, bool ROUND_OUT>
__global__ __launch_bounds__(256, 2)
void gemm_tf32(const float* __restrict__ A, const float* __restrict__ Bm,
               float* __restrict__ Cm, const float* __restrict__ bias,
               int M, int N, int K, int lda, int ldb, int ldc, float alpha)
{
    extern __shared__ float smg[];
    const uint32_t smbase = smem_u32(smg);

    const int tid  = threadIdx.x;
    const int lane = tid & 31;
    const int warp = tid >> 5;
    const int wm   = (warp >> 2) * 64;
    const int wn   = (warp & 3) * 32;
    const int m0   = blockIdx.y * 128;
    const int n0   = blockIdx.x * 128;

    auto issue = [&](int t, int s) {
        const int k0 = t * 16;
        const uint32_t abase = smbase + (s * A_ST) * 4;
        const uint32_t bbase = smbase + (3 * A_ST + s * B_ST) * 4;
#pragma unroll
        for (int u = 0; u < 2; u++) {
            int i = tid + u * 256;
            int r = i >> 2, c4 = i & 3;
            int row = m0 + r;
            int valid = (row < M);
            int rowc = valid ? row : (M - 1);
            cp_async16(abase + (r * ALD3 + c4 * 4) * 4,
                       A + (size_t)rowc * lda + k0 + c4 * 4, valid ? 16 : 0);
        }
#pragma unroll
        for (int u = 0; u < 2; u++) {
            int i = tid + u * 256;
            int r = i >> 5, c4 = i & 31;
            cp_async16(bbase + (r * BLD3 + c4 * 4) * 4,
                       Bm + (size_t)(k0 + r) * ldb + n0 + c4 * 4, 16);
        }
        CP_COMMIT();
    };

    const int ntiles = K / 16;
    issue(0, 0);
    issue(1, 1);

    float acc[4][4][4];
#pragma unroll
    for (int i = 0; i < 4; i++)
#pragma unroll
        for (int j = 0; j < 4; j++)
#pragma unroll
            for (int r = 0; r < 4; r++) acc[i][j][r] = 0.f;

    for (int t = 0; t < ntiles; t++) {
        const int s = t % 3;
        CP_WAIT(1);
        __syncthreads();
        if (t + 2 < ntiles) issue(t + 2, (t + 2) % 3);

        const float* As = smg + s * A_ST;
        const float* Bs = smg + 3 * A_ST + s * B_ST;

#pragma unroll
        for (int ks = 0; ks < 2; ks++) {
            const int kb = ks * 8;
            uint32_t af[4][4];
#pragma unroll
            for (int i = 0; i < 4; i++) {
                const float* base = &As[(wm + i * 16 + (lane >> 2)) * ALD3 + kb + (lane & 3)];
                af[i][0] = __float_as_uint(base[0]);
                af[i][1] = __float_as_uint(base[8 * ALD3]);
                af[i][2] = __float_as_uint(base[4]);
                af[i][3] = __float_as_uint(base[8 * ALD3 + 4]);
            }
#pragma unroll
            for (int j = 0; j < 4; j++) {
                uint32_t bf[2];
                const float* base = &Bs[(kb + (lane & 3)) * BLD3 + wn + j * 8 + (lane >> 2)];
                bf[0] = __float_as_uint(base[0]);
                bf[1] = __float_as_uint(base[4 * BLD3]);
#pragma unroll
                for (int i = 0; i < 4; i++)
                    mma_tf32(acc[i][j], af[i], bf);
            }
        }
        __syncthreads();
    }

#pragma unroll
    for (int i = 0; i < 4; i++) {
        const int rbase = m0 + wm + i * 16 + (lane >> 2);
#pragma unroll
        for (int h = 0; h < 2; h++) {
            const int row = rbase + h * 8;
            if (row < M) {
#pragma unroll
                for (int j = 0; j < 4; j++) {
                    const int col = n0 + wn + j * 8 + (lane & 3) * 2;
                    float2 r;
                    r.x = acc[i][j][h * 2 + 0] * alpha;
                    r.y = acc[i][j][h * 2 + 1] * alpha;
                    if (HAS_BIAS) { r.x += bias[col]; r.y += bias[col + 1]; }
                    if (ROUND_OUT) { r.x = f2tf(r.x); r.y = f2tf(r.y); }
                    *(float2*)(Cm + (size_t)row * ldc + col) = r;
                }
            }
        }
    }
}

// =============================================================
// CLS attention: 48 blocks (b,h).
// =============================================================
__global__ __launch_bounds__(256)
void cls_attn_kernel(const float* __restrict__ qkv, float* __restrict__ preout)
{
    __shared__ float sim[NN];
    __shared__ float qv[DD];
    __shared__ float red[256];
    __shared__ float accred[4 * DD];

    const int b = blockIdx.x / HH;
    const int h = blockIdx.x % HH;
    const int tid = threadIdx.x;

    if (tid < DD)
        qv[tid] = qkv[(size_t)(b * NN) * N_QKV + h * DD + tid] * SCALE;
    __syncthreads();

    for (int n = tid; n < NN; n += 256) {
        const float* kp = qkv + (size_t)(b * NN + n) * N_QKV + CC + h * DD;
        float d = 0.f;
#pragma unroll
        for (int c4 = 0; c4 < DD / 4; c4++) {
            float4 k4 = *reinterpret_cast<const float4*>(kp + c4 * 4);
            d += qv[c4*4+0]*k4.x + qv[c4*4+1]*k4.y + qv[c4*4+2]*k4.z + qv[c4*4+3]*k4.w;
        }
        sim[n] = d;
    }
    __syncthreads();

    float m = -1e30f;
    for (int n = tid; n < NN; n += 256) m = fmaxf(m, sim[n]);
    red[tid] = m; __syncthreads();
    for (int o = 128; o > 0; o >>= 1) { if (tid < o) red[tid] = fmaxf(red[tid], red[tid+o]); __syncthreads(); }
    const float mx = red[0];
    __syncthreads();

    float s = 0.f;
    for (int n = tid; n < NN; n += 256) { float e = __expf(sim[n] - mx); sim[n] = e; s += e; }
    red[tid] = s; __syncthreads();
    for (int o = 128; o > 0; o >>= 1) { if (tid < o) red[tid] += red[tid+o]; __syncthreads(); }
    const float inv = 1.f / red[0];
    __syncthreads();

    const int g = tid >> 6, dd = tid & 63;
    float a = 0.f;
    for (int n = g; n < NN; n += 4)
        a += sim[n] * qkv[(size_t)(b * NN + n) * N_QKV + 2 * CC + h * DD + dd];
    accred[g * DD + dd] = a;
    __syncthreads();
    if (tid < DD)
        preout[(size_t)(b * NN) * CC + h * DD + tid] =
            f2tf((accred[tid] + accred[DD + tid] + accred[2*DD + tid] + accred[3*DD + tid]) * inv);
}

// =============================================================
// Space attention v9: 512 threads, persistent grid 152.
// K pre-scaled (exact pow2). V row-major [224][72] (scalar loads,
// conflict-free). A-fragments (Q, Sc) and K B-fragments loaded via
// ldmatrix (LDSM) -> 2-3x fewer shared-pipe instructions.
// smem (floats):
//   Ksm[224][68] @0       = 15232
//   Vsm[224][72] @15232   = 16128
//   Qb [2][64][68] @31360 = 8704
//   Sc [64][228] @40064   = 14592
// total 54656 floats = 218624 B
// =============================================================
#define SA_KLD 68
#define SA_QLD 68
#define V_LD   72
#define SC_LD  228
#define SA_KOFF  0
#define SA_VOFF  15232
#define SA_QOFF  31360
#define SA_QBUF  4352
#define SA_SCOFF 40064
#define SA_FLOATS 54656
#define SA_SMEM (SA_FLOATS * 4)          // 218624 B
#define SA_ITEMS (2 * FF * BATCH * HH)   // 768
#define SA_T 512

__global__ __launch_bounds__(SA_T, 1)
void space_attn_kernel(const float* __restrict__ qkv, float* __restrict__ xt,
                       float* __restrict__ xd)
{
    extern __shared__ float sm[];
    float* Ksm = sm + SA_KOFF;
    float* Vsm = sm + SA_VOFF;
    float* Sc  = sm + SA_SCOFF;

    const int tid = threadIdx.x;
    const int w = tid >> 5, lane = tid & 31;
    const uint32_t smbase = smem_u32(sm);
    const uint32_t kbase  = smbase + SA_KOFF * 4;
    const uint32_t scbase = smbase + SA_SCOFF * 4;

    // ldmatrix lane decomposition
    const int t8 = lane & 7;          // row within 8
    const int g8 = lane >> 3;         // matrix index 0..3

    // one-time zeroing: K pad rows, V pad rows (196..223), Sc pad cols (196..227)
    for (int i = tid; i < 28 * 17; i += SA_T) {
        int r = 196 + i / 17, c = i % 17;
        *reinterpret_cast<float4*>(&Ksm[r * SA_KLD + c * 4]) = make_float4(0.f,0.f,0.f,0.f);
    }
    for (int i = tid; i < 28 * 18; i += SA_T) {
        int r = 196 + i / 18, c = i % 18;
        *reinterpret_cast<float4*>(&Vsm[r * V_LD + c * 4]) = make_float4(0.f,0.f,0.f,0.f);
    }
    for (int i = tid; i < 64 * 32; i += SA_T) {
        int rr = i >> 5, p = 196 + (i & 31);
        Sc[rr * SC_LD + p] = 0.f;
    }

    for (int item = blockIdx.x; item < SA_ITEMS; item += gridDim.x) {
        // remap so each CTA alternates 13/12-iter halves (152 is even)
        const int qhalf = (item & 1) ^ ((item / 152) & 1);
        const int rest  = item >> 1;
        const int f  = rest & 7;
        const int bh = rest >> 3;
        const int b  = bh / HH, h = bh % HH;
        const int niters = qhalf ? 12 : 13;
        const int qt0 = qhalf * 13;

        // K/V fill (rows < 196; pads persist as zero). K pre-scaled by SCALE.
        for (int i = tid; i < 196 * 16; i += SA_T) {
            int r = i >> 4, c4 = i & 15;
            size_t base = (size_t)(b * NN + 1 + f * PP + r) * N_QKV + h * DD + c4 * 4;
            float4 kv = *reinterpret_cast<const float4*>(qkv + base + CC);
            kv.x *= SCALE; kv.y *= SCALE; kv.z *= SCALE; kv.w *= SCALE;
            *reinterpret_cast<float4*>(&Ksm[r * SA_KLD + c4 * 4]) = kv;
            *reinterpret_cast<float4*>(&Vsm[r * V_LD + c4 * 4]) =
                *reinterpret_cast<const float4*>(qkv + base + 2 * CC);
        }

        auto issue_q = [&](int it, int buf) {
            const int q0 = (qt0 + it) * 64;
#pragma unroll
            for (int k = 0; k < 2; k++) {
                int i = tid + k * SA_T;
                int r = i >> 4, c4 = i & 15;
                int sq = q0 + r;
                int valid = (sq < SS);
                int sqc = valid ? sq : (SS - 1);
                const float* gp = qkv + (size_t)(b * NN + 1 + sqc) * N_QKV + h * DD + c4 * 4;
                uint32_t sa = smbase + (SA_QOFF + buf * SA_QBUF + r * SA_QLD + c4 * 4) * 4;
                cp_async16(sa, gp, valid ? 16 : 0);
            }
            CP_COMMIT();
        };

        issue_q(0, 0);

        for (int it = 0; it < niters; it++) {
            const int buf = it & 1;
            const int q0 = (qt0 + it) * 64;
            const uint32_t qbase = smbase + (SA_QOFF + buf * SA_QBUF) * 4;

            CP_WAIT(0);
            __syncthreads();     // Q + K/V visible; prev phase-3 done

            if (it + 1 < niters) issue_q(it + 1, buf ^ 1);

            // ---- phase 1: S[64][224] = Q @ (K*SCALE)^T; warp tile 16m x 56n ----
            const int mrow1  = (w >> 2) * 16;
            const int nbase1 = (w & 3) * 56;
            // A ldmatrix word offset (excl. kb)
            const int aoffQ = (mrow1 + t8 + (g8 & 1) * 8) * SA_QLD + (g8 >> 1) * 4;
            // K B ldmatrix (x2): lanes 0-15 significant
            const int boffK = t8 * SA_KLD + (g8 & 1) * 4;

            float acc[7][4];
#pragma unroll
            for (int nt = 0; nt < 7; nt++)
#pragma unroll
                for (int r = 0; r < 4; r++) acc[nt][r] = 0.f;

            {
                uint32_t aA[2][4], bB[2][7][2];
                auto ldfrag1 = [&](int kb, int pb) {
                    ldsm_x4(aA[pb], qbase + (aoffQ + kb) * 4);
#pragma unroll
                    for (int nt = 0; nt < 7; nt++)
                        ldsm_x2(bB[pb][nt], kbase + ((nbase1 + nt * 8) * SA_KLD + boffK + kb) * 4);
                };
                ldfrag1(0, 0);
#pragma unroll
                for (int kk = 0; kk < 8; kk++) {
                    const int pb = kk & 1;
                    if (kk < 7) ldfrag1((kk + 1) * 8, pb ^ 1);
#pragma unroll
                    for (int nt = 0; nt < 7; nt++)
                        mma_tf32(acc[nt], aA[pb], bB[pb][nt]);
                }
            }

            // store scores (already scaled via K); float2 stores, cols<196
            {
                const int r0 = mrow1 + (lane >> 2);
#pragma unroll
                for (int nt = 0; nt < 7; nt++) {
                    int col = nbase1 + nt * 8 + (lane & 3) * 2;
                    if (col < 196) {
                        *reinterpret_cast<float2*>(&Sc[r0 * SC_LD + col]) =
                            make_float2(acc[nt][0], acc[nt][1]);
                        *reinterpret_cast<float2*>(&Sc[(r0 + 8) * SC_LD + col]) =
                            make_float2(acc[nt][2], acc[nt][3]);
                    }
                }
            }
            __syncthreads();

            // ---- phase 2: softmax over p; 4 rows per warp ----
#pragma unroll
            for (int qi = 0; qi < 4; qi++) {
                const int q = w * 4 + qi;
                float v[7];
                float mx = -1e30f;
#pragma unroll
                for (int j = 0; j < 7; j++) {
                    int p = lane + 32 * j;
                    v[j] = (p < 196) ? Sc[q * SC_LD + p] : -1e30f;
                    mx = fmaxf(mx, v[j]);
                }
#pragma unroll
                for (int o = 16; o > 0; o >>= 1) mx = fmaxf(mx, __shfl_xor_sync(0xffffffffu, mx, o));
                float sum = 0.f;
#pragma unroll
                for (int j = 0; j < 7; j++) {
                    int p = lane + 32 * j;
                    float e = (p < 196) ? __expf(v[j] - mx) : 0.f;
                    v[j] = e; sum += e;
                }
#pragma unroll
                for (int o = 16; o > 0; o >>= 1) sum += __shfl_xor_sync(0xffffffffu, sum, o);
                float inv = 1.f / sum;
#pragma unroll
                for (int j = 0; j < 7; j++) {
                    int p = lane + 32 * j;
                    if (p < 196) Sc[q * SC_LD + p] = f2tf(v[j] * inv);
                }
            }
            __syncthreads();

            // ---- phase 3: out[64][64] = Sc @ V; warp tile 16m x 16n ----
            {
                const int m3  = (w >> 2) * 16;
                const int nb3 = (w & 3) * 16;
                const int aoffS = (m3 + t8 + (g8 & 1) * 8) * SC_LD + (g8 >> 1) * 4;
                float o2[2][4];
#pragma unroll
                for (int j = 0; j < 2; j++)
#pragma unroll
                    for (int r = 0; r < 4; r++) o2[j][r] = 0.f;

                uint32_t a3[2][4], b3[2][2][2];
                auto ldfrag3 = [&](int kb, int pb) {
                    ldsm_x4(a3[pb], scbase + (aoffS + kb) * 4);
#pragma unroll
                    for (int j = 0; j < 2; j++) {
                        const float* bb = &Vsm[(kb + (lane & 3)) * V_LD + nb3 + j * 8 + (lane >> 2)];
                        b3[pb][j][0] = __float_as_uint(bb[0]);
                        b3[pb][j][1] = __float_as_uint(bb[4 * V_LD]);
                    }
                };
                ldfrag3(0, 0);
#pragma unroll
                for (int kk = 0; kk < 28; kk++) {
                    const int pb = kk & 1;
                    if (kk < 27) ldfrag3((kk + 1) * 8, pb ^ 1);
                    mma_tf32(o2[0], a3[pb], b3[pb][0]);
                    mma_tf32(o2[1], a3[pb], b3[pb][1]);
                }

                const int r0 = m3 + (lane >> 2);
#pragma unroll
                for (int hh2 = 0; hh2 < 2; hh2++) {
                    const int sq = q0 + r0 + hh2 * 8;
                    if (sq < SS) {
                        float* xp = xt + ((size_t)(b * SS + sq) * FF + f) * CC + h * DD;
                        const bool diag = (sq / PP == f);
                        float* dp = xd + (size_t)(b * SS + sq) * CC + h * DD;
#pragma unroll
                        for (int j = 0; j < 2; j++) {
                            const int dv = nb3 + j * 8 + (lane & 3) * 2;
                            float2 r;
                            r.x = o2[j][hh2 * 2 + 0];
                            r.y = o2[j][hh2 * 2 + 1];
                            *reinterpret_cast<float2*>(xp + dv) = r;
                            if (diag) {
                                float2 rr = make_float2(f2tf(r.x), f2tf(r.y));
                                *reinterpret_cast<float2*>(dp + dv) = rr;
                            }
                        }
                    }
                }
            }
            __syncthreads();   // phase-3 reads done before next store/fill
        }
    }
}

// =============================================================
// gemm_G tf32: per head h, G[m,c] = sum_k q2[m,h64+k]*wkv[c,h64+k]
// =============================================================
__global__ __launch_bounds__(256)
void gemm_G_tf32(const float* __restrict__ q2, const float* __restrict__ wkv,
                 float* __restrict__ G)
{
    __shared__ float As[128 * 68];
    __shared__ float Bs[128 * 68];

    const int mt = blockIdx.x, ct = blockIdx.y, h = blockIdx.z;
    const int tid = threadIdx.x;
    const int lane = tid & 31;
    const int w = tid >> 5;

    for (int i = tid; i < 128 * 16; i += 256) {
        int r = i >> 4, c4 = i & 15;
        *reinterpret_cast<float4*>(&As[r * 68 + 4 * c4]) =
            *reinterpret_cast<const float4*>(q2 + (size_t)(mt * 128 + r) * CC + h * DD + 4 * c4);
        *reinterpret_cast<float4*>(&Bs[r * 68 + 4 * c4]) =
            *reinterpret_cast<const float4*>(wkv + (size_t)(ct * 128 + r) * (2 * CC) + h * DD + 4 * c4);
    }
    __syncthreads();

    const int wm = (w >> 2) * 64;
    const int wn = (w & 3) * 32;

    float acc[4][4][4];
#pragma unroll
    for (int i = 0; i < 4; i++)
#pragma unroll
        for (int j = 0; j < 4; j++)
#pragma unroll
            for (int r = 0; r < 4; r++) acc[i][j][r] = 0.f;

#pragma unroll
    for (int kb = 0; kb < 64; kb += 8) {
        uint32_t af[4][4], bf[4][2];
#pragma unroll
        for (int i = 0; i < 4; i++) {
            const float* base = &As[(wm + i * 16 + (lane >> 2)) * 68 + kb + (lane & 3)];
            af[i][0] = __float_as_uint(base[0]);
            af[i][1] = __float_as_uint(base[8 * 68]);
            af[i][2] = __float_as_uint(base[4]);
            af[i][3] = __float_as_uint(base[8 * 68 + 4]);
        }
#pragma unroll
        for (int j = 0; j < 4; j++) {
            const float* base = &Bs[(wn + j * 8 + (lane >> 2)) * 68 + kb + (lane & 3)];
            bf[j][0] = __float_as_uint(base[0]);
            bf[j][1] = __float_as_uint(base[4]);
        }
#pragma unroll
        for (int i = 0; i < 4; i++)
#pragma unroll
            for (int j = 0; j < 4; j++)
                mma_tf32(acc[i][j], af[i], bf[j]);
    }

#pragma unroll
    for (int i = 0; i < 4; i++) {
        const int rbase = mt * 128 + wm + i * 16 + (lane >> 2);
#pragma unroll
        for (int hh2 = 0; hh2 < 2; hh2++) {
            const size_t row = rbase + hh2 * 8;
            float* gp = G + (row * HH + h) * CC + ct * 128;
#pragma unroll
            for (int j = 0; j < 4; j++) {
                const int col = wn + j * 8 + (lane & 3) * 2;
                float2 r;
                r.x = acc[i][j][hh2 * 2 + 0];
                r.y = acc[i][j][hh2 * 2 + 1];
                *reinterpret_cast<float2*>(gp + col) = r;
            }
        }
    }
}

// =============================================================
// score_out v2: per (b,s). G in registers (warp-per-head), xt in smem.
// =============================================================
#define SO_SMEM ((FF*CC + 96 + 96) * 4)

__global__ __launch_bounds__(256)
void score_out_kernel(const float* __restrict__ xt, const float* __restrict__ G,
                      float* __restrict__ preout, float* __restrict__ attn2)
{
    extern __shared__ float sm[];
    float* xts = sm;
    float* sc  = xts + FF * CC;
    float* pr  = sc + 96;

    const int bs = blockIdx.x;
    const int b = bs / SS, s = bs % SS;
    const int tid = threadIdx.x;
    const int w = tid >> 5, l = tid & 31;

    for (int i = tid; i < FF * CC / 4; i += 256)
        reinterpret_cast<float4*>(xts)[i] =
            reinterpret_cast<const float4*>(xt)[(size_t)bs * (FF * CC / 4) + i];
    __syncthreads();

    for (int h = w; h < HH; h += 8) {
        const float4* gp = reinterpret_cast<const float4*>(G + ((size_t)bs * HH + h) * CC);
        float4 g[6];
#pragma unroll
        for (int j = 0; j < 6; j++) g[j] = gp[l + 32 * j];
#pragma unroll
        for (int f = 0; f < FF; f++) {
            const float4* xp = reinterpret_cast<const float4*>(xts + f * CC);
            float part = 0.f;
#pragma unroll
            for (int j = 0; j < 6; j++) {
                float4 x4 = xp[l + 32 * j];
                part += g[j].x*x4.x + g[j].y*x4.y + g[j].z*x4.z + g[j].w*x4.w;
            }
#pragma unroll
            for (int o = 16; o > 0; o >>= 1) part += __shfl_xor_sync(0xffffffffu, part, o);
            if (l == 0) sc[h * 8 + f] = part;
        }
    }
    __syncthreads();

    if (tid < HH) {
        int h = tid;
        float mx = -1e30f;
#pragma unroll
        for (int f = 0; f < FF; f++) mx = fmaxf(mx, sc[h * 8 + f]);
        float sum = 0.f;
        float e[FF];
#pragma unroll
        for (int f = 0; f < FF; f++) { e[f] = __expf(sc[h * 8 + f] - mx); sum += e[f]; }
        float inv = 1.f / sum;
#pragma unroll
        for (int f = 0; f < FF; f++) {
            float p = e[f] * inv;
            pr[h * 8 + f] = p;
            attn2[((size_t)(b * HH + h) * SS + s) * FF + f] = p;
        }
    }
    __syncthreads();

    for (int c = tid; c < CC; c += 256) {
        int h = c >> 6;
        float v = 0.f;
#pragma unroll
        for (int f = 0; f < FF; f++) v += pr[h * 8 + f] * xts[f * CC + c];
        preout[(size_t)(b * NN + 1 + s) * CC + c] = f2tf(v);
    }
}

// =============================================================
// host launch
// =============================================================
extern "C" void kernel_launch(void* const* d_in, const int* in_sizes, int n_in,
                              void* d_out, int out_size)
{
    const float* x      = (const float*)d_in[0];
    const float* w_qkv  = (const float*)d_in[1];
    const float* w_q    = (const float*)d_in[2];
    const float* w_kv   = (const float*)d_in[3];
    const float* w_proj = (const float*)d_in[4];
    const float* b_proj = (const float*)d_in[5];

    float *p_qkv, *p_xt, *p_xd, *p_q2, *p_G, *p_pre;
    float *p_xr, *p_wqkvr, *p_wqr, *p_wkvr, *p_wprojr;
    cudaGetSymbolAddress((void**)&p_qkv, g_qkv);
    cudaGetSymbolAddress((void**)&p_xt,  g_xt);
    cudaGetSymbolAddress((void**)&p_xd,  g_xd);
    cudaGetSymbolAddress((void**)&p_q2,  g_q2);
    cudaGetSymbolAddress((void**)&p_G,   g_G);
    cudaGetSymbolAddress((void**)&p_pre, g_pre);
    cudaGetSymbolAddress((void**)&p_xr,     g_xr);
    cudaGetSymbolAddress((void**)&p_wqkvr,  g_wqkvr);
    cudaGetSymbolAddress((void**)&p_wqr,    g_wqr);
    cudaGetSymbolAddress((void**)&p_wkvr,   g_wkvr);
    cudaGetSymbolAddress((void**)&p_wprojr, g_wprojr);

    cudaFuncSetAttribute((const void*)gemm_tf32<false, true>,  cudaFuncAttributeMaxDynamicSharedMemorySize, GT_SMEM);
    cudaFuncSetAttribute((const void*)gemm_tf32<true,  false>, cudaFuncAttributeMaxDynamicSharedMemorySize, GT_SMEM);
    cudaFuncSetAttribute(space_attn_kernel, cudaFuncAttributeMaxDynamicSharedMemorySize, SA_SMEM);
    cudaFuncSetAttribute(score_out_kernel,  cudaFuncAttributeMaxDynamicSharedMemorySize, SO_SMEM);

    float* outp  = (float*)d_out;
    float* attn2 = outp + OUT_ELEMS;

    // 0) tf32-round all GEMM inputs in one launch
    round_all<<<(RC_TOTAL + 255) / 256, 256>>>(
        x, p_xr, w_qkv, p_wqkvr, w_q, p_wqr, w_kv, p_wkvr, w_proj, p_wprojr);

    // 1) qkv = x @ w_qkv (tf32, output rounded)
    gemm_tf32<false, true><<<dim3(N_QKV/128, (M_QKV+127)/128), 256, GT_SMEM>>>(
        p_xr, p_wqkvr, p_qkv, nullptr, M_QKV, N_QKV, CC, CC, N_QKV, N_QKV, 1.f);

    // 2) cls attention -> preout row n=0 (rounded)
    cls_attn_kernel<<<BATCH*HH, 256>>>(p_qkv, p_pre);

    // 3) fused space attention (ldmatrix, persistent) -> xt, xd(rounded)
    space_attn_kernel<<<152, SA_T, SA_SMEM>>>(p_qkv, p_xt, p_xd);

    // 4) q2 = scale * x_diag @ w_q (tf32, output rounded)
    gemm_tf32<false, true><<<dim3(CC/128, M_S/128), 256, GT_SMEM>>>(
        p_xd, p_wqr, p_q2, nullptr, M_S, CC, CC, CC, CC, CC, SCALE);

    // 5) G = per-head q2 @ Wk_h^T
    gemm_G_tf32<<<dim3(M_S/128, CC/128, HH), 256>>>(p_q2, p_wkvr, p_G);

    // 6) scores + softmax(F) -> attn2; weighted xt -> preout (rounded)
    score_out_kernel<<<M_S, 256, SO_SMEM>>>(p_xt, p_G, p_pre, attn2);

    // 7) out = preout @ w_proj + b_proj (full-precision output)
    gemm_tf32<true, false><<<dim3(CC/128, (M_QKV+127)/128), 256, GT_SMEM>>>(
        p_pre, p_wprojr, outp, b_proj, M_QKV, CC, CC, CC, CC, CC, 1.f);
}

// round 14
// speedup vs baseline: 1.1825x; 1.1825x over previous
#include <cuda_runtime.h>
#include <cuda_bf16.h>
#include <math.h>
#include <stdint.h>

// ---------------- problem constants ----------------
#define BATCH 4
#define PP    196
#define FF    8
#define CC    768
#define NN    1569          // 1 + F*P
#define SS    1568          // F*P
#define HH    12
#define DD    64
#define SCALE 0.125f        // d^-0.5

#define M_QKV   (BATCH*NN)          // 6276
#define N_QKV   (3*CC)              // 2304
#define M_S     (BATCH*SS)          // 6272
#define OUT_ELEMS ((size_t)BATCH*NN*CC)   // 4,819,968

// ---------------- scratch ----------------
__device__ float g_qkv[(size_t)M_QKV * N_QKV];        // (B,N,3C) tf32-rounded
__device__ float g_xt [(size_t)M_S * FF * CC];        // (B,S,F,C)
__device__ float g_xd [(size_t)M_S * CC];             // x_diag, tf32-rounded
__device__ float g_q2 [(size_t)M_S * CC];             // tf32-rounded
__device__ float g_G  [(size_t)M_S * HH * CC];        // (B,S,h,C)
__device__ float g_pre[(size_t)M_QKV * CC];           // pre-proj, tf32-rounded
// tf32-rounded input copies
__device__ float g_xr    [(size_t)M_QKV * CC];
__device__ float g_wqkvr [(size_t)CC * 3 * CC];
__device__ float g_wqr   [(size_t)CC * CC];
__device__ float g_wkvr  [(size_t)CC * 2 * CC];
__device__ float g_wprojr[(size_t)CC * CC];

// ---------------- helpers ----------------
__device__ __forceinline__ float f2tf(float x) {
    uint32_t u;
    asm("cvt.rna.tf32.f32 %0, %1;" : "=r"(u) : "f"(x));
    return __uint_as_float(u);
}

__device__ __forceinline__ void mma_tf32(float* c, const uint32_t* a, const uint32_t* b) {
    asm volatile("mma.sync.aligned.m16n8k8.row.col.f32.tf32.tf32.f32 "
        "{%0,%1,%2,%3}, {%4,%5,%6,%7}, {%8,%9}, {%0,%1,%2,%3};"
        : "+f"(c[0]), "+f"(c[1]), "+f"(c[2]), "+f"(c[3])
        : "r"(a[0]), "r"(a[1]), "r"(a[2]), "r"(a[3]), "r"(b[0]), "r"(b[1]));
}

__device__ __forceinline__ uint32_t smem_u32(const void* p) {
    return (uint32_t)__cvta_generic_to_shared(p);
}

__device__ __forceinline__ void cp_async16(uint32_t saddr, const void* gptr, int src_bytes) {
    asm volatile("cp.async.cg.shared.global [%0], [%1], 16, %2;\n"
                 :: "r"(saddr), "l"(gptr), "r"(src_bytes));
}
#define CP_COMMIT() asm volatile("cp.async.commit_group;\n" ::: "memory")
#define CP_WAIT(n)  asm volatile("cp.async.wait_group %0;\n" :: "n"(n) : "memory")

// =============================================================
// round_all: tf32-round all 5 GEMM inputs in ONE launch.
// =============================================================
#define RC_N0 1204992
#define RC_N1 442368
#define RC_N2 147456
#define RC_N3 294912
#define RC_N4 147456
#define RC_TOTAL (RC_N0+RC_N1+RC_N2+RC_N3+RC_N4)

__global__ __launch_bounds__(256)
void round_all(const float* __restrict__ s0, float* __restrict__ d0,
               const float* __restrict__ s1, float* __restrict__ d1,
               const float* __restrict__ s2, float* __restrict__ d2,
               const float* __restrict__ s3, float* __restrict__ d3,
               const float* __restrict__ s4, float* __restrict__ d4)
{
    int i = blockIdx.x * 256 + threadIdx.x;
    if (i >= RC_TOTAL) return;
    const float4* src; float4* dst; int off = i;
    if (off < RC_N0)                { src = (const float4*)s0; dst = (float4*)d0; }
    else if ((off -= RC_N0) < RC_N1){ src = (const float4*)s1; dst = (float4*)d1; }
    else if ((off -= RC_N1) < RC_N2){ src = (const float4*)s2; dst = (float4*)d2; }
    else if ((off -= RC_N2) < RC_N3){ src = (const float4*)s3; dst = (float4*)d3; }
    else                            { off -= RC_N3; src = (const float4*)s4; dst = (float4*)d4; }
    float4 v = src[off];
    v.x = f2tf(v.x); v.y = f2tf(v.y); v.z = f2tf(v.z); v.w = f2tf(v.w);
    dst[off] = v;
}

// =============================================================
// TF32 GEMM v3: cp.async 3-stage pipeline, 128x128x16, 2 CTAs/SM.
// =============================================================
#define ALD3 20
#define BLD3 136
#define A_ST (128 * ALD3)
#define B_ST (16 * BLD3)
#define GT_SMEM ((3 * A_ST + 3 * B_ST) * 4)

template<bool HAS_BIAS, bool ROUND_OUT>
__global__ __launch_bounds__(256, 2)
void gemm_tf32(const float* __restrict__ A, const float* __restrict__ Bm,
               float* __restrict__ Cm, const float* __restrict__ bias,
               int M, int N, int K, int lda, int ldb, int ldc, float alpha)
{
    extern __shared__ float smg[];
    const uint32_t smbase = smem_u32(smg);

    const int tid  = threadIdx.x;
    const int lane = tid & 31;
    const int warp = tid >> 5;
    const int wm   = (warp >> 2) * 64;
    const int wn   = (warp & 3) * 32;
    const int m0   = blockIdx.y * 128;
    const int n0   = blockIdx.x * 128;

    auto issue = [&](int t, int s) {
        const int k0 = t * 16;
        const uint32_t abase = smbase + (s * A_ST) * 4;
        const uint32_t bbase = smbase + (3 * A_ST + s * B_ST) * 4;
#pragma unroll
        for (int u = 0; u < 2; u++) {
            int i = tid + u * 256;
            int r = i >> 2, c4 = i & 3;
            int row = m0 + r;
            int valid = (row < M);
            int rowc = valid ? row : (M - 1);
            cp_async16(abase + (r * ALD3 + c4 * 4) * 4,
                       A + (size_t)rowc * lda + k0 + c4 * 4, valid ? 16 : 0);
        }
#pragma unroll
        for (int u = 0; u < 2; u++) {
            int i = tid + u * 256;
            int r = i >> 5, c4 = i & 31;
            cp_async16(bbase + (r * BLD3 + c4 * 4) * 4,
                       Bm + (size_t)(k0 + r) * ldb + n0 + c4 * 4, 16);
        }
        CP_COMMIT();
    };

    const int ntiles = K / 16;
    issue(0, 0);
    issue(1, 1);

    float acc[4][4][4];
#pragma unroll
    for (int i = 0; i < 4; i++)
#pragma unroll
        for (int j = 0; j < 4; j++)
#pragma unroll
            for (int r = 0; r < 4; r++) acc[i][j][r] = 0.f;

    for (int t = 0; t < ntiles; t++) {
        const int s = t % 3;
        CP_WAIT(1);
        __syncthreads();
        if (t + 2 < ntiles) issue(t + 2, (t + 2) % 3);

        const float* As = smg + s * A_ST;
        const float* Bs = smg + 3 * A_ST + s * B_ST;

#pragma unroll
        for (int ks = 0; ks < 2; ks++) {
            const int kb = ks * 8;
            uint32_t af[4][4];
#pragma unroll
            for (int i = 0; i < 4; i++) {
                const float* base = &As[(wm + i * 16 + (lane >> 2)) * ALD3 + kb + (lane & 3)];
                af[i][0] = __float_as_uint(base[0]);
                af[i][1] = __float_as_uint(base[8 * ALD3]);
                af[i][2] = __float_as_uint(base[4]);
                af[i][3] = __float_as_uint(base[8 * ALD3 + 4]);
            }
#pragma unroll
            for (int j = 0; j < 4; j++) {
                uint32_t bf[2];
                const float* base = &Bs[(kb + (lane & 3)) * BLD3 + wn + j * 8 + (lane >> 2)];
                bf[0] = __float_as_uint(base[0]);
                bf[1] = __float_as_uint(base[4 * BLD3]);
#pragma unroll
                for (int i = 0; i < 4; i++)
                    mma_tf32(acc[i][j], af[i], bf);
            }
        }
        __syncthreads();
    }

#pragma unroll
    for (int i = 0; i < 4; i++) {
        const int rbase = m0 + wm + i * 16 + (lane >> 2);
#pragma unroll
        for (int h = 0; h < 2; h++) {
            const int row = rbase + h * 8;
            if (row < M) {
#pragma unroll
                for (int j = 0; j < 4; j++) {
                    const int col = n0 + wn + j * 8 + (lane & 3) * 2;
                    float2 r;
                    r.x = acc[i][j][h * 2 + 0] * alpha;
                    r.y = acc[i][j][h * 2 + 1] * alpha;
                    if (HAS_BIAS) { r.x += bias[col]; r.y += bias[col + 1]; }
                    if (ROUND_OUT) { r.x = f2tf(r.x); r.y = f2tf(r.y); }
                    *(float2*)(Cm + (size_t)row * ldc + col) = r;
                }
            }
        }
    }
}

// =============================================================
// CLS attention: 48 blocks (b,h).
// =============================================================
__global__ __launch_bounds__(256)
void cls_attn_kernel(const float* __restrict__ qkv, float* __restrict__ preout)
{
    __shared__ float sim[NN];
    __shared__ float qv[DD];
    __shared__ float red[256];
    __shared__ float accred[4 * DD];

    const int b = blockIdx.x / HH;
    const int h = blockIdx.x % HH;
    const int tid = threadIdx.x;

    if (tid < DD)
        qv[tid] = qkv[(size_t)(b * NN) * N_QKV + h * DD + tid] * SCALE;
    __syncthreads();

    for (int n = tid; n < NN; n += 256) {
        const float* kp = qkv + (size_t)(b * NN + n) * N_QKV + CC + h * DD;
        float d = 0.f;
#pragma unroll
        for (int c4 = 0; c4 < DD / 4; c4++) {
            float4 k4 = *reinterpret_cast<const float4*>(kp + c4 * 4);
            d += qv[c4*4+0]*k4.x + qv[c4*4+1]*k4.y + qv[c4*4+2]*k4.z + qv[c4*4+3]*k4.w;
        }
        sim[n] = d;
    }
    __syncthreads();

    float m = -1e30f;
    for (int n = tid; n < NN; n += 256) m = fmaxf(m, sim[n]);
    red[tid] = m; __syncthreads();
    for (int o = 128; o > 0; o >>= 1) { if (tid < o) red[tid] = fmaxf(red[tid], red[tid+o]); __syncthreads(); }
    const float mx = red[0];
    __syncthreads();

    float s = 0.f;
    for (int n = tid; n < NN; n += 256) { float e = __expf(sim[n] - mx); sim[n] = e; s += e; }
    red[tid] = s; __syncthreads();
    for (int o = 128; o > 0; o >>= 1) { if (tid < o) red[tid] += red[tid+o]; __syncthreads(); }
    const float inv = 1.f / red[0];
    __syncthreads();

    const int g = tid >> 6, dd = tid & 63;
    float a = 0.f;
    for (int n = g; n < NN; n += 4)
        a += sim[n] * qkv[(size_t)(b * NN + n) * N_QKV + 2 * CC + h * DD + dd];
    accred[g * DD + dd] = a;
    __syncthreads();
    if (tid < DD)
        preout[(size_t)(b * NN) * CC + h * DD + tid] =
            f2tf((accred[tid] + accred[DD + tid] + accred[2*DD + tid] + accred[3*DD + tid]) * inv);
}

// =============================================================
// Space attention v10 (= v8 + permuted-K LDS.64 B-fragments).
// 512 threads, persistent grid 152.
// K stored pre-scaled AND column-permuted within 8-col groups:
//   perm(c) = (c&~7) | ((c&3)<<1) | ((c>>2)&1)
// so the B-fragment pair (kb+j, kb+j+4) is adjacent -> one LDS.64.
// V row-major [224][72]; Sc plain layout.
// smem (floats):
//   Ksm[224][68] @0       = 15232
//   Vsm[224][72] @15232   = 16128
//   Qb [2][64][68] @31360 = 8704
//   Sc [64][228] @40064   = 14592
// =============================================================
#define SA_KLD 68
#define SA_QLD 68
#define V_LD   72
#define SC_LD  228
#define SA_KOFF  0
#define SA_VOFF  15232
#define SA_QOFF  31360
#define SA_QBUF  4352
#define SA_SCOFF 40064
#define SA_FLOATS 54656
#define SA_SMEM (SA_FLOATS * 4)          // 218624 B
#define SA_ITEMS (2 * FF * BATCH * HH)   // 768
#define SA_T 512

__global__ __launch_bounds__(SA_T, 1)
void space_attn_kernel(const float* __restrict__ qkv, float* __restrict__ xt,
                       float* __restrict__ xd)
{
    extern __shared__ float sm[];
    float* Ksm = sm + SA_KOFF;
    float* Vsm = sm + SA_VOFF;
    float* Qb  = sm + SA_QOFF;
    float* Sc  = sm + SA_SCOFF;

    const int tid = threadIdx.x;
    const int w = tid >> 5, lane = tid & 31;
    const uint32_t smbase = smem_u32(sm);

    // one-time zeroing: K pad rows, V pad rows (196..223), Sc pad cols (196..227)
    for (int i = tid; i < 28 * 17; i += SA_T) {
        int r = 196 + i / 17, c = i % 17;
        *reinterpret_cast<float4*>(&Ksm[r * SA_KLD + c * 4]) = make_float4(0.f,0.f,0.f,0.f);
    }
    for (int i = tid; i < 28 * 18; i += SA_T) {
        int r = 196 + i / 18, c = i % 18;
        *reinterpret_cast<float4*>(&Vsm[r * V_LD + c * 4]) = make_float4(0.f,0.f,0.f,0.f);
    }
    for (int i = tid; i < 64 * 32; i += SA_T) {
        int rr = i >> 5, p = 196 + (i & 31);
        Sc[rr * SC_LD + p] = 0.f;
    }
    __syncthreads();

    for (int item = blockIdx.x; item < SA_ITEMS; item += gridDim.x) {
        const int qhalf = (item & 1) ^ ((item / 152) & 1);
        const int rest  = item >> 1;
        const int f  = rest & 7;
        const int bh = rest >> 3;
        const int b  = bh / HH, h = bh % HH;
        const int niters = qhalf ? 12 : 13;
        const int qt0 = qhalf * 13;

        // K/V fill (rows < 196). K pre-scaled + column-permuted.
        for (int i = tid; i < 196 * 16; i += SA_T) {
            int r = i >> 4, c4 = i & 15;
            size_t base = (size_t)(b * NN + 1 + f * PP + r) * N_QKV + h * DD + c4 * 4;
            float4 kv = *reinterpret_cast<const float4*>(qkv + base + CC);
            // cols 4c4..4c4+3 -> group g=(c4>>1)*8, within off=(c4&1)*4+t -> pos 2t+(c4&1)
            float* kbp = &Ksm[r * SA_KLD + (c4 >> 1) * 8 + (c4 & 1)];
            kbp[0] = kv.x * SCALE;
            kbp[2] = kv.y * SCALE;
            kbp[4] = kv.z * SCALE;
            kbp[6] = kv.w * SCALE;
            *reinterpret_cast<float4*>(&Vsm[r * V_LD + c4 * 4]) =
                *reinterpret_cast<const float4*>(qkv + base + 2 * CC);
        }

        auto issue_q = [&](int it, int buf) {
            const int q0 = (qt0 + it) * 64;
#pragma unroll
            for (int k = 0; k < 2; k++) {
                int i = tid + k * SA_T;
                int r = i >> 4, c4 = i & 15;
                int sq = q0 + r;
                int valid = (sq < SS);
                int sqc = valid ? sq : (SS - 1);
                const float* gp = qkv + (size_t)(b * NN + 1 + sqc) * N_QKV + h * DD + c4 * 4;
                uint32_t sa = smbase + (SA_QOFF + buf * SA_QBUF + r * SA_QLD + c4 * 4) * 4;
                cp_async16(sa, gp, valid ? 16 : 0);
            }
            CP_COMMIT();
        };

        issue_q(0, 0);

        for (int it = 0; it < niters; it++) {
            const int buf = it & 1;
            const int q0 = (qt0 + it) * 64;
            const float* Qsm = Qb + buf * SA_QBUF;

            CP_WAIT(0);
            __syncthreads();     // Q + K/V visible; prev phase-3 done (orders Sc/V reuse)

            if (it + 1 < niters) issue_q(it + 1, buf ^ 1);

            // ---- phase 1: S[64][224] = Q @ (K*SCALE)^T; warp tile 16m x 56n ----
            const int mrow1  = (w >> 2) * 16;
            const int nbase1 = (w & 3) * 56;
            float acc[7][4];
#pragma unroll
            for (int nt = 0; nt < 7; nt++)
#pragma unroll
                for (int r = 0; r < 4; r++) acc[nt][r] = 0.f;

            {
                uint32_t aA[2][4], bB[2][7][2];
                auto ldfrag1 = [&](int kb, int pb) {
                    const float* ab = &Qsm[(mrow1 + (lane >> 2)) * SA_QLD + kb + (lane & 3)];
                    aA[pb][0] = __float_as_uint(ab[0]);
                    aA[pb][1] = __float_as_uint(ab[8 * SA_QLD]);
                    aA[pb][2] = __float_as_uint(ab[4]);
                    aA[pb][3] = __float_as_uint(ab[8 * SA_QLD + 4]);
#pragma unroll
                    for (int nt = 0; nt < 7; nt++) {
                        // permuted K: pair (kb+j, kb+j+4) lives at kb+2j, kb+2j+1
                        float2 v = *reinterpret_cast<const float2*>(
                            &Ksm[(nbase1 + nt * 8 + (lane >> 2)) * SA_KLD + kb + (lane & 3) * 2]);
                        bB[pb][nt][0] = __float_as_uint(v.x);
                        bB[pb][nt][1] = __float_as_uint(v.y);
                    }
                };
                ldfrag1(0, 0);
#pragma unroll
                for (int kk = 0; kk < 8; kk++) {
                    const int pb = kk & 1;
                    if (kk < 7) ldfrag1((kk + 1) * 8, pb ^ 1);
#pragma unroll
                    for (int nt = 0; nt < 7; nt++)
                        mma_tf32(acc[nt], aA[pb], bB[pb][nt]);
                }
            }

            // store scores; float2 stores, cols<196
            {
                const int r0 = mrow1 + (lane >> 2);
#pragma unroll
                for (int nt = 0; nt < 7; nt++) {
                    int col = nbase1 + nt * 8 + (lane & 3) * 2;
                    if (col < 196) {
                        *reinterpret_cast<float2*>(&Sc[r0 * SC_LD + col]) =
                            make_float2(acc[nt][0], acc[nt][1]);
                        *reinterpret_cast<float2*>(&Sc[(r0 + 8) * SC_LD + col]) =
                            make_float2(acc[nt][2], acc[nt][3]);
                    }
                }
            }
            __syncthreads();

            // ---- phase 2: softmax over p; 4 rows per warp ----
#pragma unroll
            for (int qi = 0; qi < 4; qi++) {
                const int q = w * 4 + qi;
                float v[7];
                float mx = -1e30f;
#pragma unroll
                for (int j = 0; j < 7; j++) {
                    int p = lane + 32 * j;
                    v[j] = (p < 196) ? Sc[q * SC_LD + p] : -1e30f;
                    mx = fmaxf(mx, v[j]);
                }
#pragma unroll
                for (int o = 16; o > 0; o >>= 1) mx = fmaxf(mx, __shfl_xor_sync(0xffffffffu, mx, o));
                float sum = 0.f;
#pragma unroll
                for (int j = 0; j < 7; j++) {
                    int p = lane + 32 * j;
                    float e = (p < 196) ? __expf(v[j] - mx) : 0.f;
                    v[j] = e; sum += e;
                }
#pragma unroll
                for (int o = 16; o > 0; o >>= 1) sum += __shfl_xor_sync(0xffffffffu, sum, o);
                float inv = 1.f / sum;
#pragma unroll
                for (int j = 0; j < 7; j++) {
                    int p = lane + 32 * j;
                    if (p < 196) Sc[q * SC_LD + p] = f2tf(v[j] * inv);
                }
            }
            __syncthreads();

            // ---- phase 3: out[64][64] = Sc @ V; warp tile 16m x 16n ----
            {
                const int m3  = (w >> 2) * 16;
                const int nb3 = (w & 3) * 16;
                float o2[2][4];
#pragma unroll
                for (int j = 0; j < 2; j++)
#pragma unroll
                    for (int r = 0; r < 4; r++) o2[j][r] = 0.f;

                uint32_t a3[2][4], b3[2][2][2];
                auto ldfrag3 = [&](int kb, int pb) {
                    const float* ab = &Sc[(m3 + (lane >> 2)) * SC_LD + kb + (lane & 3)];
                    a3[pb][0] = __float_as_uint(ab[0]);
                    a3[pb][1] = __float_as_uint(ab[8 * SC_LD]);
                    a3[pb][2] = __float_as_uint(ab[4]);
                    a3[pb][3] = __float_as_uint(ab[8 * SC_LD + 4]);
#pragma unroll
                    for (int j = 0; j < 2; j++) {
                        const float* bb = &Vsm[(kb + (lane & 3)) * V_LD + nb3 + j * 8 + (lane >> 2)];
                        b3[pb][j][0] = __float_as_uint(bb[0]);
                        b3[pb][j][1] = __float_as_uint(bb[4 * V_LD]);
                    }
                };
                ldfrag3(0, 0);
#pragma unroll
                for (int kk = 0; kk < 28; kk++) {
                    const int pb = kk & 1;
                    if (kk < 27) ldfrag3((kk + 1) * 8, pb ^ 1);
                    mma_tf32(o2[0], a3[pb], b3[pb][0]);
                    mma_tf32(o2[1], a3[pb], b3[pb][1]);
                }

                const int r0 = m3 + (lane >> 2);
#pragma unroll
                for (int hh2 = 0; hh2 < 2; hh2++) {
                    const int sq = q0 + r0 + hh2 * 8;
                    if (sq < SS) {
                        float* xp = xt + ((size_t)(b * SS + sq) * FF + f) * CC + h * DD;
                        const bool diag = (sq / PP == f);
                        float* dp = xd + (size_t)(b * SS + sq) * CC + h * DD;
#pragma unroll
                        for (int j = 0; j < 2; j++) {
                            const int dv = nb3 + j * 8 + (lane & 3) * 2;
                            float2 r;
                            r.x = o2[j][hh2 * 2 + 0];
                            r.y = o2[j][hh2 * 2 + 1];
                            *reinterpret_cast<float2*>(xp + dv) = r;
                            if (diag) {
                                float2 rr = make_float2(f2tf(r.x), f2tf(r.y));
                                *reinterpret_cast<float2*>(dp + dv) = rr;
                            }
                        }
                    }
                }
            }
            // no bottom barrier: next iteration's top barrier orders
            // this phase-3's Sc/V reads before any new Sc/Q writes
        }
        __syncthreads();   // protect K/V refill for next item vs this item's phase-3
    }
}

// =============================================================
// gemm_G tf32: per head h, G[m,c] = sum_k q2[m,h64+k]*wkv[c,h64+k]
// =============================================================
__global__ __launch_bounds__(256)
void gemm_G_tf32(const float* __restrict__ q2, const float* __restrict__ wkv,
                 float* __restrict__ G)
{
    __shared__ float As[128 * 68];
    __shared__ float Bs[128 * 68];

    const int mt = blockIdx.x, ct = blockIdx.y, h = blockIdx.z;
    const int tid = threadIdx.x;
    const int lane = tid & 31;
    const int w = tid >> 5;

    for (int i = tid; i < 128 * 16; i += 256) {
        int r = i >> 4, c4 = i & 15;
        *reinterpret_cast<float4*>(&As[r * 68 + 4 * c4]) =
            *reinterpret_cast<const float4*>(q2 + (size_t)(mt * 128 + r) * CC + h * DD + 4 * c4);
        *reinterpret_cast<float4*>(&Bs[r * 68 + 4 * c4]) =
            *reinterpret_cast<const float4*>(wkv + (size_t)(ct * 128 + r) * (2 * CC) + h * DD + 4 * c4);
    }
    __syncthreads();

    const int wm = (w >> 2) * 64;
    const int wn = (w & 3) * 32;

    float acc[4][4][4];
#pragma unroll
    for (int i = 0; i < 4; i++)
#pragma unroll
        for (int j = 0; j < 4; j++)
#pragma unroll
            for (int r = 0; r < 4; r++) acc[i][j][r] = 0.f;

#pragma unroll
    for (int kb = 0; kb < 64; kb += 8) {
        uint32_t af[4][4], bf[4][2];
#pragma unroll
        for (int i = 0; i < 4; i++) {
            const float* base = &As[(wm + i * 16 + (lane >> 2)) * 68 + kb + (lane & 3)];
            af[i][0] = __float_as_uint(base[0]);
            af[i][1] = __float_as_uint(base[8 * 68]);
            af[i][2] = __float_as_uint(base[4]);
            af[i][3] = __float_as_uint(base[8 * 68 + 4]);
        }
#pragma unroll
        for (int j = 0; j < 4; j++) {
            const float* base = &Bs[(wn + j * 8 + (lane >> 2)) * 68 + kb + (lane & 3)];
            bf[j][0] = __float_as_uint(base[0]);
            bf[j][1] = __float_as_uint(base[4]);
        }
#pragma unroll
        for (int i = 0; i < 4; i++)
#pragma unroll
            for (int j = 0; j < 4; j++)
                mma_tf32(acc[i][j], af[i], bf[j]);
    }

#pragma unroll
    for (int i = 0; i < 4; i++) {
        const int rbase = mt * 128 + wm + i * 16 + (lane >> 2);
#pragma unroll
        for (int hh2 = 0; hh2 < 2; hh2++) {
            const size_t row = rbase + hh2 * 8;
            float* gp = G + (row * HH + h) * CC + ct * 128;
#pragma unroll
            for (int j = 0; j < 4; j++) {
                const int col = wn + j * 8 + (lane & 3) * 2;
                float2 r;
                r.x = acc[i][j][hh2 * 2 + 0];
                r.y = acc[i][j][hh2 * 2 + 1];
                *reinterpret_cast<float2*>(gp + col) = r;
            }
        }
    }
}

// =============================================================
// score_out v2: per (b,s). G in registers (warp-per-head), xt in smem.
// =============================================================
#define SO_SMEM ((FF*CC + 96 + 96) * 4)

__global__ __launch_bounds__(256)
void score_out_kernel(const float* __restrict__ xt, const float* __restrict__ G,
                      float* __restrict__ preout, float* __restrict__ attn2)
{
    extern __shared__ float sm[];
    float* xts = sm;
    float* sc  = xts + FF * CC;
    float* pr  = sc + 96;

    const int bs = blockIdx.x;
    const int b = bs / SS, s = bs % SS;
    const int tid = threadIdx.x;
    const int w = tid >> 5, l = tid & 31;

    for (int i = tid; i < FF * CC / 4; i += 256)
        reinterpret_cast<float4*>(xts)[i] =
            reinterpret_cast<const float4*>(xt)[(size_t)bs * (FF * CC / 4) + i];
    __syncthreads();

    for (int h = w; h < HH; h += 8) {
        const float4* gp = reinterpret_cast<const float4*>(G + ((size_t)bs * HH + h) * CC);
        float4 g[6];
#pragma unroll
        for (int j = 0; j < 6; j++) g[j] = gp[l + 32 * j];
#pragma unroll
        for (int f = 0; f < FF; f++) {
            const float4* xp = reinterpret_cast<const float4*>(xts + f * CC);
            float part = 0.f;
#pragma unroll
            for (int j = 0; j < 6; j++) {
                float4 x4 = xp[l + 32 * j];
                part += g[j].x*x4.x + g[j].y*x4.y + g[j].z*x4.z + g[j].w*x4.w;
            }
#pragma unroll
            for (int o = 16; o > 0; o >>= 1) part += __shfl_xor_sync(0xffffffffu, part, o);
            if (l == 0) sc[h * 8 + f] = part;
        }
    }
    __syncthreads();

    if (tid < HH) {
        int h = tid;
        float mx = -1e30f;
#pragma unroll
        for (int f = 0; f < FF; f++) mx = fmaxf(mx, sc[h * 8 + f]);
        float sum = 0.f;
        float e[FF];
#pragma unroll
        for (int f = 0; f < FF; f++) { e[f] = __expf(sc[h * 8 + f] - mx); sum += e[f]; }
        float inv = 1.f / sum;
#pragma unroll
        for (int f = 0; f < FF; f++) {
            float p = e[f] * inv;
            pr[h * 8 + f] = p;
            attn2[((size_t)(b * HH + h) * SS + s) * FF + f] = p;
        }
    }
    __syncthreads();

    for (int c = tid; c < CC; c += 256) {
        int h = c >> 6;
        float v = 0.f;
#pragma unroll
        for (int f = 0; f < FF; f++) v += pr[h * 8 + f] * xts[f * CC + c];
        preout[(size_t)(b * NN + 1 + s) * CC + c] = f2tf(v);
    }
}

// =============================================================
// host launch
// =============================================================
extern "C" void kernel_launch(void* const* d_in, const int* in_sizes, int n_in,
                              void* d_out, int out_size)
{
    const float* x      = (const float*)d_in[0];
    const float* w_qkv  = (const float*)d_in[1];
    const float* w_q    = (const float*)d_in[2];
    const float* w_kv   = (const float*)d_in[3];
    const float* w_proj = (const float*)d_in[4];
    const float* b_proj = (const float*)d_in[5];

    float *p_qkv, *p_xt, *p_xd, *p_q2, *p_G, *p_pre;
    float *p_xr, *p_wqkvr, *p_wqr, *p_wkvr, *p_wprojr;
    cudaGetSymbolAddress((void**)&p_qkv, g_qkv);
    cudaGetSymbolAddress((void**)&p_xt,  g_xt);
    cudaGetSymbolAddress((void**)&p_xd,  g_xd);
    cudaGetSymbolAddress((void**)&p_q2,  g_q2);
    cudaGetSymbolAddress((void**)&p_G,   g_G);
    cudaGetSymbolAddress((void**)&p_pre, g_pre);
    cudaGetSymbolAddress((void**)&p_xr,     g_xr);
    cudaGetSymbolAddress((void**)&p_wqkvr,  g_wqkvr);
    cudaGetSymbolAddress((void**)&p_wqr,    g_wqr);
    cudaGetSymbolAddress((void**)&p_wkvr,   g_wkvr);
    cudaGetSymbolAddress((void**)&p_wprojr, g_wprojr);

    cudaFuncSetAttribute((const void*)gemm_tf32<false, true>,  cudaFuncAttributeMaxDynamicSharedMemorySize, GT_SMEM);
    cudaFuncSetAttribute((const void*)gemm_tf32<true,  false>, cudaFuncAttributeMaxDynamicSharedMemorySize, GT_SMEM);
    cudaFuncSetAttribute(space_attn_kernel, cudaFuncAttributeMaxDynamicSharedMemorySize, SA_SMEM);
    cudaFuncSetAttribute(score_out_kernel,  cudaFuncAttributeMaxDynamicSharedMemorySize, SO_SMEM);

    float* outp  = (float*)d_out;
    float* attn2 = outp + OUT_ELEMS;

    // 0) tf32-round all GEMM inputs in one launch
    round_all<<<(RC_TOTAL + 255) / 256, 256>>>(
        x, p_xr, w_qkv, p_wqkvr, w_q, p_wqr, w_kv, p_wkvr, w_proj, p_wprojr);

    // 1) qkv = x @ w_qkv (tf32, output rounded)
    gemm_tf32<false, true><<<dim3(N_QKV/128, (M_QKV+127)/128), 256, GT_SMEM>>>(
        p_xr, p_wqkvr, p_qkv, nullptr, M_QKV, N_QKV, CC, CC, N_QKV, N_QKV, 1.f);

    // 2) cls attention -> preout row n=0 (rounded)
    cls_attn_kernel<<<BATCH*HH, 256>>>(p_qkv, p_pre);

    // 3) fused space attention (permuted-K, persistent) -> xt, xd(rounded)
    space_attn_kernel<<<152, SA_T, SA_SMEM>>>(p_qkv, p_xt, p_xd);

    // 4) q2 = scale * x_diag @ w_q (tf32, output rounded)
    gemm_tf32<false, true><<<dim3(CC/128, M_S/128), 256, GT_SMEM>>>(
        p_xd, p_wqr, p_q2, nullptr, M_S, CC, CC, CC, CC, CC, SCALE);

    // 5) G = per-head q2 @ Wk_h^T
    gemm_G_tf32<<<dim3(M_S/128, CC/128, HH), 256>>>(p_q2, p_wkvr, p_G);

    // 6) scores + softmax(F) -> attn2; weighted xt -> preout (rounded)
    score_out_kernel<<<M_S, 256, SO_SMEM>>>(p_xt, p_G, p_pre, attn2);

    // 7) out = preout @ w_proj + b_proj (full-precision output)
    gemm_tf32<true, false><<<dim3(CC/128, (M_QKV+127)/128), 256, GT_SMEM>>>(
        p_pre, p_wprojr, outp, b_proj, M_QKV, CC, CC, CC, CC, CC, 1.f);
}

// round 15
// speedup vs baseline: 1.2594x; 1.0650x over previous
#include <cuda_runtime.h>
#include <cuda_bf16.h>
#include <math.h>
#include <stdint.h>

// ---------------- problem constants ----------------
#define BATCH 4
#define PP    196
#define FF    8
#define CC    768
#define NN    1569          // 1 + F*P
#define SS    1568          // F*P
#define HH    12
#define DD    64
#define SCALE 0.125f        // d^-0.5

#define M_QKV   (BATCH*NN)          // 6276
#define N_QKV   (3*CC)              // 2304
#define M_S     (BATCH*SS)          // 6272
#define OUT_ELEMS ((size_t)BATCH*NN*CC)   // 4,819,968

// ---------------- scratch ----------------
__device__ float g_qkv[(size_t)M_QKV * N_QKV];        // (B,N,3C) tf32-rounded
__device__ float g_xt [(size_t)M_S * FF * CC];        // (B,S,F,C)
__device__ float g_xd [(size_t)M_S * CC];             // x_diag, tf32-rounded
__device__ float g_q2 [(size_t)M_S * CC];             // tf32-rounded
__device__ float g_G  [(size_t)M_S * HH * CC];        // (B,S,h,C)
__device__ float g_pre[(size_t)M_QKV * CC];           // pre-proj, tf32-rounded
// tf32-rounded input copies
__device__ float g_xr    [(size_t)M_QKV * CC];
__device__ float g_wqkvr [(size_t)CC * 3 * CC];
__device__ float g_wqr   [(size_t)CC * CC];
__device__ float g_wkvr  [(size_t)CC * 2 * CC];
__device__ float g_wprojr[(size_t)CC * CC];

// ---------------- helpers ----------------
__device__ __forceinline__ float f2tf(float x) {
    uint32_t u;
    asm("cvt.rna.tf32.f32 %0, %1;" : "=r"(u) : "f"(x));
    return __uint_as_float(u);
}

__device__ __forceinline__ void mma_tf32(float* c, const uint32_t* a, const uint32_t* b) {
    asm volatile("mma.sync.aligned.m16n8k8.row.col.f32.tf32.tf32.f32 "
        "{%0,%1,%2,%3}, {%4,%5,%6,%7}, {%8,%9}, {%0,%1,%2,%3};"
        : "+f"(c[0]), "+f"(c[1]), "+f"(c[2]), "+f"(c[3])
        : "r"(a[0]), "r"(a[1]), "r"(a[2]), "r"(a[3]), "r"(b[0]), "r"(b[1]));
}

__device__ __forceinline__ uint32_t smem_u32(const void* p) {
    return (uint32_t)__cvta_generic_to_shared(p);
}

__device__ __forceinline__ void cp_async16(uint32_t saddr, const void* gptr, int src_bytes) {
    asm volatile("cp.async.cg.shared.global [%0], [%1], 16, %2;\n"
                 :: "r"(saddr), "l"(gptr), "r"(src_bytes));
}
#define CP_COMMIT() asm volatile("cp.async.commit_group;\n" ::: "memory")
#define CP_WAIT(n)  asm volatile("cp.async.wait_group %0;\n" :: "n"(n) : "memory")

// =============================================================
// round_all: tf32-round all 5 GEMM inputs in ONE launch.
// =============================================================
#define RC_N0 1204992
#define RC_N1 442368
#define RC_N2 147456
#define RC_N3 294912
#define RC_N4 147456
#define RC_TOTAL (RC_N0+RC_N1+RC_N2+RC_N3+RC_N4)

__global__ __launch_bounds__(256)
void round_all(const float* __restrict__ s0, float* __restrict__ d0,
               const float* __restrict__ s1, float* __restrict__ d1,
               const float* __restrict__ s2, float* __restrict__ d2,
               const float* __restrict__ s3, float* __restrict__ d3,
               const float* __restrict__ s4, float* __restrict__ d4)
{
    int i = blockIdx.x * 256 + threadIdx.x;
    if (i >= RC_TOTAL) return;
    const float4* src; float4* dst; int off = i;
    if (off < RC_N0)                { src = (const float4*)s0; dst = (float4*)d0; }
    else if ((off -= RC_N0) < RC_N1){ src = (const float4*)s1; dst = (float4*)d1; }
    else if ((off -= RC_N1) < RC_N2){ src = (const float4*)s2; dst = (float4*)d2; }
    else if ((off -= RC_N2) < RC_N3){ src = (const float4*)s3; dst = (float4*)d3; }
    else                            { off -= RC_N3; src = (const float4*)s4; dst = (float4*)d4; }
    float4 v = src[off];
    v.x = f2tf(v.x); v.y = f2tf(v.y); v.z = f2tf(v.z); v.w = f2tf(v.w);
    dst[off] = v;
}

// =============================================================
// TF32 GEMM v3: cp.async 3-stage pipeline, 128x128x16, 2 CTAs/SM.
// =============================================================
#define ALD3 20
#define BLD3 136
#define A_ST (128 * ALD3)
#define B_ST (16 * BLD3)
#define GT_SMEM ((3 * A_ST + 3 * B_ST) * 4)

template<bool HAS_BIAS, bool ROUND_OUT>
__global__ __launch_bounds__(256, 2)
void gemm_tf32(const float* __restrict__ A, const float* __restrict__ Bm,
               float* __restrict__ Cm, const float* __restrict__ bias,
               int M, int N, int K, int lda, int ldb, int ldc, float alpha)
{
    extern __shared__ float smg[];
    const uint32_t smbase = smem_u32(smg);

    const int tid  = threadIdx.x;
    const int lane = tid & 31;
    const int warp = tid >> 5;
    const int wm   = (warp >> 2) * 64;
    const int wn   = (warp & 3) * 32;
    const int m0   = blockIdx.y * 128;
    const int n0   = blockIdx.x * 128;

    auto issue = [&](int t, int s) {
        const int k0 = t * 16;
        const uint32_t abase = smbase + (s * A_ST) * 4;
        const uint32_t bbase = smbase + (3 * A_ST + s * B_ST) * 4;
#pragma unroll
        for (int u = 0; u < 2; u++) {
            int i = tid + u * 256;
            int r = i >> 2, c4 = i & 3;
            int row = m0 + r;
            int valid = (row < M);
            int rowc = valid ? row : (M - 1);
            cp_async16(abase + (r * ALD3 + c4 * 4) * 4,
                       A + (size_t)rowc * lda + k0 + c4 * 4, valid ? 16 : 0);
        }
#pragma unroll
        for (int u = 0; u < 2; u++) {
            int i = tid + u * 256;
            int r = i >> 5, c4 = i & 31;
            cp_async16(bbase + (r * BLD3 + c4 * 4) * 4,
                       Bm + (size_t)(k0 + r) * ldb + n0 + c4 * 4, 16);
        }
        CP_COMMIT();
    };

    const int ntiles = K / 16;
    issue(0, 0);
    issue(1, 1);

    float acc[4][4][4];
#pragma unroll
    for (int i = 0; i < 4; i++)
#pragma unroll
        for (int j = 0; j < 4; j++)
#pragma unroll
            for (int r = 0; r < 4; r++) acc[i][j][r] = 0.f;

    for (int t = 0; t < ntiles; t++) {
        const int s = t % 3;
        CP_WAIT(1);
        __syncthreads();
        if (t + 2 < ntiles) issue(t + 2, (t + 2) % 3);

        const float* As = smg + s * A_ST;
        const float* Bs = smg + 3 * A_ST + s * B_ST;

#pragma unroll
        for (int ks = 0; ks < 2; ks++) {
            const int kb = ks * 8;
            uint32_t af[4][4];
#pragma unroll
            for (int i = 0; i < 4; i++) {
                const float* base = &As[(wm + i * 16 + (lane >> 2)) * ALD3 + kb + (lane & 3)];
                af[i][0] = __float_as_uint(base[0]);
                af[i][1] = __float_as_uint(base[8 * ALD3]);
                af[i][2] = __float_as_uint(base[4]);
                af[i][3] = __float_as_uint(base[8 * ALD3 + 4]);
            }
#pragma unroll
            for (int j = 0; j < 4; j++) {
                uint32_t bf[2];
                const float* base = &Bs[(kb + (lane & 3)) * BLD3 + wn + j * 8 + (lane >> 2)];
                bf[0] = __float_as_uint(base[0]);
                bf[1] = __float_as_uint(base[4 * BLD3]);
#pragma unroll
                for (int i = 0; i < 4; i++)
                    mma_tf32(acc[i][j], af[i], bf);
            }
        }
        __syncthreads();
    }

#pragma unroll
    for (int i = 0; i < 4; i++) {
        const int rbase = m0 + wm + i * 16 + (lane >> 2);
#pragma unroll
        for (int h = 0; h < 2; h++) {
            const int row = rbase + h * 8;
            if (row < M) {
#pragma unroll
                for (int j = 0; j < 4; j++) {
                    const int col = n0 + wn + j * 8 + (lane & 3) * 2;
                    float2 r;
                    r.x = acc[i][j][h * 2 + 0] * alpha;
                    r.y = acc[i][j][h * 2 + 1] * alpha;
                    if (HAS_BIAS) { r.x += bias[col]; r.y += bias[col + 1]; }
                    if (ROUND_OUT) { r.x = f2tf(r.x); r.y = f2tf(r.y); }
                    *(float2*)(Cm + (size_t)row * ldc + col) = r;
                }
            }
        }
    }
}

// =============================================================
// CLS attention: 48 blocks (b,h).
// =============================================================
__global__ __launch_bounds__(256)
void cls_attn_kernel(const float* __restrict__ qkv, float* __restrict__ preout)
{
    __shared__ float sim[NN];
    __shared__ float qv[DD];
    __shared__ float red[256];
    __shared__ float accred[4 * DD];

    const int b = blockIdx.x / HH;
    const int h = blockIdx.x % HH;
    const int tid = threadIdx.x;

    if (tid < DD)
        qv[tid] = qkv[(size_t)(b * NN) * N_QKV + h * DD + tid] * SCALE;
    __syncthreads();

    for (int n = tid; n < NN; n += 256) {
        const float* kp = qkv + (size_t)(b * NN + n) * N_QKV + CC + h * DD;
        float d = 0.f;
#pragma unroll
        for (int c4 = 0; c4 < DD / 4; c4++) {
            float4 k4 = *reinterpret_cast<const float4*>(kp + c4 * 4);
            d += qv[c4*4+0]*k4.x + qv[c4*4+1]*k4.y + qv[c4*4+2]*k4.z + qv[c4*4+3]*k4.w;
        }
        sim[n] = d;
    }
    __syncthreads();

    float m = -1e30f;
    for (int n = tid; n < NN; n += 256) m = fmaxf(m, sim[n]);
    red[tid] = m; __syncthreads();
    for (int o = 128; o > 0; o >>= 1) { if (tid < o) red[tid] = fmaxf(red[tid], red[tid+o]); __syncthreads(); }
    const float mx = red[0];
    __syncthreads();

    float s = 0.f;
    for (int n = tid; n < NN; n += 256) { float e = __expf(sim[n] - mx); sim[n] = e; s += e; }
    red[tid] = s; __syncthreads();
    for (int o = 128; o > 0; o >>= 1) { if (tid < o) red[tid] += red[tid+o]; __syncthreads(); }
    const float inv = 1.f / red[0];
    __syncthreads();

    const int g = tid >> 6, dd = tid & 63;
    float a = 0.f;
    for (int n = g; n < NN; n += 4)
        a += sim[n] * qkv[(size_t)(b * NN + n) * N_QKV + 2 * CC + h * DD + dd];
    accred[g * DD + dd] = a;
    __syncthreads();
    if (tid < DD)
        preout[(size_t)(b * NN) * CC + h * DD + tid] =
            f2tf((accred[tid] + accred[DD + tid] + accred[2*DD + tid] + accred[3*DD + tid]) * inv);
}

// =============================================================
// Space attention v11: EXACT v8 compute (proven 466us), finer
// work units for load balance: unit = (quarter, f, bh), 1536 units.
// quarter 0: q-tiles [0,7); 1:[7,13); 2:[13,19); 3:[19,25).
// quarter rotated per rest so 7-tile quarters spread across CTAs.
// 512 threads, persistent grid 152.
// smem (floats):
//   Ksm[224][68] @0       = 15232
//   Vsm[224][72] @15232   = 16128
//   Qb [2][64][68] @31360 = 8704
//   Sc [64][228] @40064   = 14592
// =============================================================
#define SA_KLD 68
#define SA_QLD 68
#define V_LD   72
#define SC_LD  228
#define SA_KOFF  0
#define SA_VOFF  15232
#define SA_QOFF  31360
#define SA_QBUF  4352
#define SA_SCOFF 40064
#define SA_FLOATS 54656
#define SA_SMEM (SA_FLOATS * 4)          // 218624 B
#define SA_UNITS (4 * FF * BATCH * HH)   // 1536
#define SA_T 512

__global__ __launch_bounds__(SA_T, 1)
void space_attn_kernel(const float* __restrict__ qkv, float* __restrict__ xt,
                       float* __restrict__ xd)
{
    extern __shared__ float sm[];
    float* Ksm = sm + SA_KOFF;
    float* Vsm = sm + SA_VOFF;
    float* Qb  = sm + SA_QOFF;
    float* Sc  = sm + SA_SCOFF;

    const int tid = threadIdx.x;
    const int w = tid >> 5, lane = tid & 31;
    const uint32_t smbase = smem_u32(sm);

    // one-time zeroing: K pad rows, V pad rows (196..223), Sc pad cols (196..227)
    for (int i = tid; i < 28 * 17; i += SA_T) {
        int r = 196 + i / 17, c = i % 17;
        *reinterpret_cast<float4*>(&Ksm[r * SA_KLD + c * 4]) = make_float4(0.f,0.f,0.f,0.f);
    }
    for (int i = tid; i < 28 * 18; i += SA_T) {
        int r = 196 + i / 18, c = i % 18;
        *reinterpret_cast<float4*>(&Vsm[r * V_LD + c * 4]) = make_float4(0.f,0.f,0.f,0.f);
    }
    for (int i = tid; i < 64 * 32; i += SA_T) {
        int rr = i >> 5, p = 196 + (i & 31);
        Vsm[0 * V_LD + 0] += 0.f;   // no-op keeps structure clear
        Sc[rr * SC_LD + p] = 0.f;
    }
    __syncthreads();

    for (int unit = blockIdx.x; unit < SA_UNITS; unit += gridDim.x) {
        const int rest = unit >> 2;
        const int quarter = ((unit & 3) + rest) & 3;   // rotated: bijective per rest
        const int f  = rest & 7;
        const int bh = rest >> 3;
        const int b  = bh / HH, h = bh % HH;
        const int qt0    = quarter * 6 + (quarter > 0 ? 1 : 0);
        const int niters = (quarter == 0) ? 7 : 6;

        // K/V fill (rows < 196; pads persist as zero). K pre-scaled by SCALE.
        for (int i = tid; i < 196 * 16; i += SA_T) {
            int r = i >> 4, c4 = i & 15;
            size_t base = (size_t)(b * NN + 1 + f * PP + r) * N_QKV + h * DD + c4 * 4;
            float4 kv = *reinterpret_cast<const float4*>(qkv + base + CC);
            kv.x *= SCALE; kv.y *= SCALE; kv.z *= SCALE; kv.w *= SCALE;
            *reinterpret_cast<float4*>(&Ksm[r * SA_KLD + c4 * 4]) = kv;
            *reinterpret_cast<float4*>(&Vsm[r * V_LD + c4 * 4]) =
                *reinterpret_cast<const float4*>(qkv + base + 2 * CC);
        }

        auto issue_q = [&](int it, int buf) {
            const int q0 = (qt0 + it) * 64;
#pragma unroll
            for (int k = 0; k < 2; k++) {
                int i = tid + k * SA_T;
                int r = i >> 4, c4 = i & 15;
                int sq = q0 + r;
                int valid = (sq < SS);
                int sqc = valid ? sq : (SS - 1);
                const float* gp = qkv + (size_t)(b * NN + 1 + sqc) * N_QKV + h * DD + c4 * 4;
                uint32_t sa = smbase + (SA_QOFF + buf * SA_QBUF + r * SA_QLD + c4 * 4) * 4;
                cp_async16(sa, gp, valid ? 16 : 0);
            }
            CP_COMMIT();
        };

        issue_q(0, 0);

        for (int it = 0; it < niters; it++) {
            const int buf = it & 1;
            const int q0 = (qt0 + it) * 64;
            const float* Qsm = Qb + buf * SA_QBUF;

            CP_WAIT(0);
            __syncthreads();     // Q + K/V visible; prev phase-3 done

            if (it + 1 < niters) issue_q(it + 1, buf ^ 1);

            // ---- phase 1: S[64][224] = Q @ (K*SCALE)^T; warp tile 16m x 56n ----
            const int mrow1  = (w >> 2) * 16;
            const int nbase1 = (w & 3) * 56;
            float acc[7][4];
#pragma unroll
            for (int nt = 0; nt < 7; nt++)
#pragma unroll
                for (int r = 0; r < 4; r++) acc[nt][r] = 0.f;

            {
                uint32_t aA[2][4], bB[2][7][2];
                auto ldfrag1 = [&](int kb, int pb) {
                    const float* ab = &Qsm[(mrow1 + (lane >> 2)) * SA_QLD + kb + (lane & 3)];
                    aA[pb][0] = __float_as_uint(ab[0]);
                    aA[pb][1] = __float_as_uint(ab[8 * SA_QLD]);
                    aA[pb][2] = __float_as_uint(ab[4]);
                    aA[pb][3] = __float_as_uint(ab[8 * SA_QLD + 4]);
#pragma unroll
                    for (int nt = 0; nt < 7; nt++) {
                        const float* bb = &Ksm[(nbase1 + nt * 8 + (lane >> 2)) * SA_KLD + kb + (lane & 3)];
                        bB[pb][nt][0] = __float_as_uint(bb[0]);
                        bB[pb][nt][1] = __float_as_uint(bb[4]);
                    }
                };
                ldfrag1(0, 0);
#pragma unroll
                for (int kk = 0; kk < 8; kk++) {
                    const int pb = kk & 1;
                    if (kk < 7) ldfrag1((kk + 1) * 8, pb ^ 1);
#pragma unroll
                    for (int nt = 0; nt < 7; nt++)
                        mma_tf32(acc[nt], aA[pb], bB[pb][nt]);
                }
            }

            // store scores (already scaled via K); float2 stores, cols<196
            {
                const int r0 = mrow1 + (lane >> 2);
#pragma unroll
                for (int nt = 0; nt < 7; nt++) {
                    int col = nbase1 + nt * 8 + (lane & 3) * 2;
                    if (col < 196) {
                        *reinterpret_cast<float2*>(&Sc[r0 * SC_LD + col]) =
                            make_float2(acc[nt][0], acc[nt][1]);
                        *reinterpret_cast<float2*>(&Sc[(r0 + 8) * SC_LD + col]) =
                            make_float2(acc[nt][2], acc[nt][3]);
                    }
                }
            }
            __syncthreads();

            // ---- phase 2: softmax over p; 4 rows per warp ----
#pragma unroll
            for (int qi = 0; qi < 4; qi++) {
                const int q = w * 4 + qi;
                float v[7];
                float mx = -1e30f;
#pragma unroll
                for (int j = 0; j < 7; j++) {
                    int p = lane + 32 * j;
                    v[j] = (p < 196) ? Sc[q * SC_LD + p] : -1e30f;
                    mx = fmaxf(mx, v[j]);
                }
#pragma unroll
                for (int o = 16; o > 0; o >>= 1) mx = fmaxf(mx, __shfl_xor_sync(0xffffffffu, mx, o));
                float sum = 0.f;
#pragma unroll
                for (int j = 0; j < 7; j++) {
                    int p = lane + 32 * j;
                    float e = (p < 196) ? __expf(v[j] - mx) : 0.f;
                    v[j] = e; sum += e;
                }
#pragma unroll
                for (int o = 16; o > 0; o >>= 1) sum += __shfl_xor_sync(0xffffffffu, sum, o);
                float inv = 1.f / sum;
#pragma unroll
                for (int j = 0; j < 7; j++) {
                    int p = lane + 32 * j;
                    if (p < 196) Sc[q * SC_LD + p] = f2tf(v[j] * inv);
                }
            }
            __syncthreads();

            // ---- phase 3: out[64][64] = Sc @ V; warp tile 16m x 16n ----
            {
                const int m3  = (w >> 2) * 16;
                const int nb3 = (w & 3) * 16;
                float o2[2][4];
#pragma unroll
                for (int j = 0; j < 2; j++)
#pragma unroll
                    for (int r = 0; r < 4; r++) o2[j][r] = 0.f;

                uint32_t a3[2][4], b3[2][2][2];
                auto ldfrag3 = [&](int kb, int pb) {
                    const float* ab = &Sc[(m3 + (lane >> 2)) * SC_LD + kb + (lane & 3)];
                    a3[pb][0] = __float_as_uint(ab[0]);
                    a3[pb][1] = __float_as_uint(ab[8 * SC_LD]);
                    a3[pb][2] = __float_as_uint(ab[4]);
                    a3[pb][3] = __float_as_uint(ab[8 * SC_LD + 4]);
#pragma unroll
                    for (int j = 0; j < 2; j++) {
                        const float* bb = &Vsm[(kb + (lane & 3)) * V_LD + nb3 + j * 8 + (lane >> 2)];
                        b3[pb][j][0] = __float_as_uint(bb[0]);
                        b3[pb][j][1] = __float_as_uint(bb[4 * V_LD]);
                    }
                };
                ldfrag3(0, 0);
#pragma unroll
                for (int kk = 0; kk < 28; kk++) {
                    const int pb = kk & 1;
                    if (kk < 27) ldfrag3((kk + 1) * 8, pb ^ 1);
                    mma_tf32(o2[0], a3[pb], b3[pb][0]);
                    mma_tf32(o2[1], a3[pb], b3[pb][1]);
                }

                const int r0 = m3 + (lane >> 2);
#pragma unroll
                for (int hh2 = 0; hh2 < 2; hh2++) {
                    const int sq = q0 + r0 + hh2 * 8;
                    if (sq < SS) {
                        float* xp = xt + ((size_t)(b * SS + sq) * FF + f) * CC + h * DD;
                        const bool diag = (sq / PP == f);
                        float* dp = xd + (size_t)(b * SS + sq) * CC + h * DD;
#pragma unroll
                        for (int j = 0; j < 2; j++) {
                            const int dv = nb3 + j * 8 + (lane & 3) * 2;
                            float2 r;
                            r.x = o2[j][hh2 * 2 + 0];
                            r.y = o2[j][hh2 * 2 + 1];
                            *reinterpret_cast<float2*>(xp + dv) = r;
                            if (diag) {
                                float2 rr = make_float2(f2tf(r.x), f2tf(r.y));
                                *reinterpret_cast<float2*>(dp + dv) = rr;
                            }
                        }
                    }
                }
            }
            __syncthreads();   // phase-3 reads done before next store/fill
        }
    }
}

// =============================================================
// gemm_G tf32: per head h, G[m,c] = sum_k q2[m,h64+k]*wkv[c,h64+k]
// =============================================================
__global__ __launch_bounds__(256)
void gemm_G_tf32(const float* __restrict__ q2, const float* __restrict__ wkv,
                 float* __restrict__ G)
{
    __shared__ float As[128 * 68];
    __shared__ float Bs[128 * 68];

    const int mt = blockIdx.x, ct = blockIdx.y, h = blockIdx.z;
    const int tid = threadIdx.x;
    const int lane = tid & 31;
    const int w = tid >> 5;

    for (int i = tid; i < 128 * 16; i += 256) {
        int r = i >> 4, c4 = i & 15;
        *reinterpret_cast<float4*>(&As[r * 68 + 4 * c4]) =
            *reinterpret_cast<const float4*>(q2 + (size_t)(mt * 128 + r) * CC + h * DD + 4 * c4);
        *reinterpret_cast<float4*>(&Bs[r * 68 + 4 * c4]) =
            *reinterpret_cast<const float4*>(wkv + (size_t)(ct * 128 + r) * (2 * CC) + h * DD + 4 * c4);
    }
    __syncthreads();

    const int wm = (w >> 2) * 64;
    const int wn = (w & 3) * 32;

    float acc[4][4][4];
#pragma unroll
    for (int i = 0; i < 4; i++)
#pragma unroll
        for (int j = 0; j < 4; j++)
#pragma unroll
            for (int r = 0; r < 4; r++) acc[i][j][r] = 0.f;

#pragma unroll
    for (int kb = 0; kb < 64; kb += 8) {
        uint32_t af[4][4], bf[4][2];
#pragma unroll
        for (int i = 0; i < 4; i++) {
            const float* base = &As[(wm + i * 16 + (lane >> 2)) * 68 + kb + (lane & 3)];
            af[i][0] = __float_as_uint(base[0]);
            af[i][1] = __float_as_uint(base[8 * 68]);
            af[i][2] = __float_as_uint(base[4]);
            af[i][3] = __float_as_uint(base[8 * 68 + 4]);
        }
#pragma unroll
        for (int j = 0; j < 4; j++) {
            const float* base = &Bs[(wn + j * 8 + (lane >> 2)) * 68 + kb + (lane & 3)];
            bf[j][0] = __float_as_uint(base[0]);
            bf[j][1] = __float_as_uint(base[4]);
        }
#pragma unroll
        for (int i = 0; i < 4; i++)
#pragma unroll
            for (int j = 0; j < 4; j++)
                mma_tf32(acc[i][j], af[i], bf[j]);
    }

#pragma unroll
    for (int i = 0; i < 4; i++) {
        const int rbase = mt * 128 + wm + i * 16 + (lane >> 2);
#pragma unroll
        for (int hh2 = 0; hh2 < 2; hh2++) {
            const size_t row = rbase + hh2 * 8;
            float* gp = G + (row * HH + h) * CC + ct * 128;
#pragma unroll
            for (int j = 0; j < 4; j++) {
                const int col = wn + j * 8 + (lane & 3) * 2;
                float2 r;
                r.x = acc[i][j][hh2 * 2 + 0];
                r.y = acc[i][j][hh2 * 2 + 1];
                *reinterpret_cast<float2*>(gp + col) = r;
            }
        }
    }
}

// =============================================================
// score_out v2: per (b,s). G in registers (warp-per-head), xt in smem.
// =============================================================
#define SO_SMEM ((FF*CC + 96 + 96) * 4)

__global__ __launch_bounds__(256)
void score_out_kernel(const float* __restrict__ xt, const float* __restrict__ G,
                      float* __restrict__ preout, float* __restrict__ attn2)
{
    extern __shared__ float sm[];
    float* xts = sm;
    float* sc  = xts + FF * CC;
    float* pr  = sc + 96;

    const int bs = blockIdx.x;
    const int b = bs / SS, s = bs % SS;
    const int tid = threadIdx.x;
    const int w = tid >> 5, l = tid & 31;

    for (int i = tid; i < FF * CC / 4; i += 256)
        reinterpret_cast<float4*>(xts)[i] =
            reinterpret_cast<const float4*>(xt)[(size_t)bs * (FF * CC / 4) + i];
    __syncthreads();

    for (int h = w; h < HH; h += 8) {
        const float4* gp = reinterpret_cast<const float4*>(G + ((size_t)bs * HH + h) * CC);
        float4 g[6];
#pragma unroll
        for (int j = 0; j < 6; j++) g[j] = gp[l + 32 * j];
#pragma unroll
        for (int f = 0; f < FF; f++) {
            const float4* xp = reinterpret_cast<const float4*>(xts + f * CC);
            float part = 0.f;
#pragma unroll
            for (int j = 0; j < 6; j++) {
                float4 x4 = xp[l + 32 * j];
                part += g[j].x*x4.x + g[j].y*x4.y + g[j].z*x4.z + g[j].w*x4.w;
            }
#pragma unroll
            for (int o = 16; o > 0; o >>= 1) part += __shfl_xor_sync(0xffffffffu, part, o);
            if (l == 0) sc[h * 8 + f] = part;
        }
    }
    __syncthreads();

    if (tid < HH) {
        int h = tid;
        float mx = -1e30f;
#pragma unroll
        for (int f = 0; f < FF; f++) mx = fmaxf(mx, sc[h * 8 + f]);
        float sum = 0.f;
        float e[FF];
#pragma unroll
        for (int f = 0; f < FF; f++) { e[f] = __expf(sc[h * 8 + f] - mx); sum += e[f]; }
        float inv = 1.f / sum;
#pragma unroll
        for (int f = 0; f < FF; f++) {
            float p = e[f] * inv;
            pr[h * 8 + f] = p;
            attn2[((size_t)(b * HH + h) * SS + s) * FF + f] = p;
        }
    }
    __syncthreads();

    for (int c = tid; c < CC; c += 256) {
        int h = c >> 6;
        float v = 0.f;
#pragma unroll
        for (int f = 0; f < FF; f++) v += pr[h * 8 + f] * xts[f * CC + c];
        preout[(size_t)(b * NN + 1 + s) * CC + c] = f2tf(v);
    }
}

// =============================================================
// host launch
// =============================================================
extern "C" void kernel_launch(void* const* d_in, const int* in_sizes, int n_in,
                              void* d_out, int out_size)
{
    const float* x      = (const float*)d_in[0];
    const float* w_qkv  = (const float*)d_in[1];
    const float* w_q    = (const float*)d_in[2];
    const float* w_kv   = (const float*)d_in[3];
    const float* w_proj = (const float*)d_in[4];
    const float* b_proj = (const float*)d_in[5];

    float *p_qkv, *p_xt, *p_xd, *p_q2, *p_G, *p_pre;
    float *p_xr, *p_wqkvr, *p_wqr, *p_wkvr, *p_wprojr;
    cudaGetSymbolAddress((void**)&p_qkv, g_qkv);
    cudaGetSymbolAddress((void**)&p_xt,  g_xt);
    cudaGetSymbolAddress((void**)&p_xd,  g_xd);
    cudaGetSymbolAddress((void**)&p_q2,  g_q2);
    cudaGetSymbolAddress((void**)&p_G,   g_G);
    cudaGetSymbolAddress((void**)&p_pre, g_pre);
    cudaGetSymbolAddress((void**)&p_xr,     g_xr);
    cudaGetSymbolAddress((void**)&p_wqkvr,  g_wqkvr);
    cudaGetSymbolAddress((void**)&p_wqr,    g_wqr);
    cudaGetSymbolAddress((void**)&p_wkvr,   g_wkvr);
    cudaGetSymbolAddress((void**)&p_wprojr, g_wprojr);

    cudaFuncSetAttribute((const void*)gemm_tf32<false, true>,  cudaFuncAttributeMaxDynamicSharedMemorySize, GT_SMEM);
    cudaFuncSetAttribute((const void*)gemm_tf32<true,  false>, cudaFuncAttributeMaxDynamicSharedMemorySize, GT_SMEM);
    cudaFuncSetAttribute(space_attn_kernel, cudaFuncAttributeMaxDynamicSharedMemorySize, SA_SMEM);
    cudaFuncSetAttribute(score_out_kernel,  cudaFuncAttributeMaxDynamicSharedMemorySize, SO_SMEM);

    float* outp  = (float*)d_out;
    float* attn2 = outp + OUT_ELEMS;

    // 0) tf32-round all GEMM inputs in one launch
    round_all<<<(RC_TOTAL + 255) / 256, 256>>>(
        x, p_xr, w_qkv, p_wqkvr, w_q, p_wqr, w_kv, p_wkvr, w_proj, p_wprojr);

    // 1) qkv = x @ w_qkv (tf32, output rounded)
    gemm_tf32<false, true><<<dim3(N_QKV/128, (M_QKV+127)/128), 256, GT_SMEM>>>(
        p_xr, p_wqkvr, p_qkv, nullptr, M_QKV, N_QKV, CC, CC, N_QKV, N_QKV, 1.f);

    // 2) cls attention -> preout row n=0 (rounded)
    cls_attn_kernel<<<BATCH*HH, 256>>>(p_qkv, p_pre);

    // 3) fused space attention (balanced quarter units) -> xt, xd(rounded)
    space_attn_kernel<<<152, SA_T, SA_SMEM>>>(p_qkv, p_xt, p_xd);

    // 4) q2 = scale * x_diag @ w_q (tf32, output rounded)
    gemm_tf32<false, true><<<dim3(CC/128, M_S/128), 256, GT_SMEM>>>(
        p_xd, p_wqr, p_q2, nullptr, M_S, CC, CC, CC, CC, CC, SCALE);

    // 5) G = per-head q2 @ Wk_h^T
    gemm_G_tf32<<<dim3(M_S/128, CC/128, HH), 256>>>(p_q2, p_wkvr, p_G);

    // 6) scores + softmax(F) -> attn2; weighted xt -> preout (rounded)
    score_out_kernel<<<M_S, 256, SO_SMEM>>>(p_xt, p_G, p_pre, attn2);

    // 7) out = preout @ w_proj + b_proj (full-precision output)
    gemm_tf32<true, false><<<dim3(CC/128, (M_QKV+127)/128), 256, GT_SMEM>>>(
        p_pre, p_wprojr, outp, b_proj, M_QKV, CC, CC, CC, CC, CC, 1.f);
}

// round 16
// speedup vs baseline: 1.2905x; 1.0247x over previous
#include <cuda_runtime.h>
#include <cuda_bf16.h>
#include <math.h>
#include <stdint.h>

// ---------------- problem constants ----------------
#define BATCH 4
#define PP    196
#define FF    8
#define CC    768
#define NN    1569          // 1 + F*P
#define SS    1568          // F*P
#define HH    12
#define DD    64
#define SCALE 0.125f        // d^-0.5

#define M_QKV   (BATCH*NN)          // 6276
#define N_QKV   (3*CC)              // 2304
#define M_S     (BATCH*SS)          // 6272
#define OUT_ELEMS ((size_t)BATCH*NN*CC)   // 4,819,968

// ---------------- scratch ----------------
__device__ float g_qkv[(size_t)M_QKV * N_QKV];        // (B,N,3C) tf32-rounded
__device__ float g_xt [(size_t)M_S * FF * CC];        // (B,S,F,C)
__device__ float g_xd [(size_t)M_S * CC];             // x_diag, tf32-rounded
__device__ float g_q2 [(size_t)M_S * CC];             // tf32-rounded
__device__ float g_G  [(size_t)M_S * HH * CC];        // (B,S,h,C)
__device__ float g_pre[(size_t)M_QKV * CC];           // pre-proj, tf32-rounded
// tf32-rounded input copies
__device__ float g_xr    [(size_t)M_QKV * CC];
__device__ float g_wqkvr [(size_t)CC * 3 * CC];
__device__ float g_wqr   [(size_t)CC * CC];
__device__ float g_wkvr  [(size_t)CC * 2 * CC];
__device__ float g_wprojr[(size_t)CC * CC];

// ---------------- helpers ----------------
__device__ __forceinline__ float f2tf(float x) {
    uint32_t u;
    asm("cvt.rna.tf32.f32 %0, %1;" : "=r"(u) : "f"(x));
    return __uint_as_float(u);
}

__device__ __forceinline__ void mma_tf32(float* c, const uint32_t* a, const uint32_t* b) {
    asm volatile("mma.sync.aligned.m16n8k8.row.col.f32.tf32.tf32.f32 "
        "{%0,%1,%2,%3}, {%4,%5,%6,%7}, {%8,%9}, {%0,%1,%2,%3};"
        : "+f"(c[0]), "+f"(c[1]), "+f"(c[2]), "+f"(c[3])
        : "r"(a[0]), "r"(a[1]), "r"(a[2]), "r"(a[3]), "r"(b[0]), "r"(b[1]));
}

__device__ __forceinline__ uint32_t smem_u32(const void* p) {
    return (uint32_t)__cvta_generic_to_shared(p);
}

__device__ __forceinline__ void cp_async16(uint32_t saddr, const void* gptr, int src_bytes) {
    asm volatile("cp.async.cg.shared.global [%0], [%1], 16, %2;\n"
                 :: "r"(saddr), "l"(gptr), "r"(src_bytes));
}
#define CP_COMMIT() asm volatile("cp.async.commit_group;\n" ::: "memory")
#define CP_WAIT(n)  asm volatile("cp.async.wait_group %0;\n" :: "n"(n) : "memory")

// =============================================================
// round_all: tf32-round all 5 GEMM inputs in ONE launch.
// =============================================================
#define RC_N0 1204992
#define RC_N1 442368
#define RC_N2 147456
#define RC_N3 294912
#define RC_N4 147456
#define RC_TOTAL (RC_N0+RC_N1+RC_N2+RC_N3+RC_N4)

__global__ __launch_bounds__(256)
void round_all(const float* __restrict__ s0, float* __restrict__ d0,
               const float* __restrict__ s1, float* __restrict__ d1,
               const float* __restrict__ s2, float* __restrict__ d2,
               const float* __restrict__ s3, float* __restrict__ d3,
               const float* __restrict__ s4, float* __restrict__ d4)
{
    int i = blockIdx.x * 256 + threadIdx.x;
    if (i >= RC_TOTAL) return;
    const float4* src; float4* dst; int off = i;
    if (off < RC_N0)                { src = (const float4*)s0; dst = (float4*)d0; }
    else if ((off -= RC_N0) < RC_N1){ src = (const float4*)s1; dst = (float4*)d1; }
    else if ((off -= RC_N1) < RC_N2){ src = (const float4*)s2; dst = (float4*)d2; }
    else if ((off -= RC_N2) < RC_N3){ src = (const float4*)s3; dst = (float4*)d3; }
    else                            { off -= RC_N3; src = (const float4*)s4; dst = (float4*)d4; }
    float4 v = src[off];
    v.x = f2tf(v.x); v.y = f2tf(v.y); v.z = f2tf(v.z); v.w = f2tf(v.w);
    dst[off] = v;
}

// =============================================================
// TF32 GEMM v3: cp.async 3-stage pipeline, 128x128x16, 2 CTAs/SM.
// =============================================================
#define ALD3 20
#define BLD3 136
#define A_ST (128 * ALD3)
#define B_ST (16 * BLD3)
#define GT_SMEM ((3 * A_ST + 3 * B_ST) * 4)

template<bool HAS_BIAS, bool ROUND_OUT>
__global__ __launch_bounds__(256, 2)
void gemm_tf32(const float* __restrict__ A, const float* __restrict__ Bm,
               float* __restrict__ Cm, const float* __restrict__ bias,
               int M, int N, int K, int lda, int ldb, int ldc, float alpha)
{
    extern __shared__ float smg[];
    const uint32_t smbase = smem_u32(smg);

    const int tid  = threadIdx.x;
    const int lane = tid & 31;
    const int warp = tid >> 5;
    const int wm   = (warp >> 2) * 64;
    const int wn   = (warp & 3) * 32;
    const int m0   = blockIdx.y * 128;
    const int n0   = blockIdx.x * 128;

    auto issue = [&](int t, int s) {
        const int k0 = t * 16;
        const uint32_t abase = smbase + (s * A_ST) * 4;
        const uint32_t bbase = smbase + (3 * A_ST + s * B_ST) * 4;
#pragma unroll
        for (int u = 0; u < 2; u++) {
            int i = tid + u * 256;
            int r = i >> 2, c4 = i & 3;
            int row = m0 + r;
            int valid = (row < M);
            int rowc = valid ? row : (M - 1);
            cp_async16(abase + (r * ALD3 + c4 * 4) * 4,
                       A + (size_t)rowc * lda + k0 + c4 * 4, valid ? 16 : 0);
        }
#pragma unroll
        for (int u = 0; u < 2; u++) {
            int i = tid + u * 256;
            int r = i >> 5, c4 = i & 31;
            cp_async16(bbase + (r * BLD3 + c4 * 4) * 4,
                       Bm + (size_t)(k0 + r) * ldb + n0 + c4 * 4, 16);
        }
        CP_COMMIT();
    };

    const int ntiles = K / 16;
    issue(0, 0);
    issue(1, 1);

    float acc[4][4][4];
#pragma unroll
    for (int i = 0; i < 4; i++)
#pragma unroll
        for (int j = 0; j < 4; j++)
#pragma unroll
            for (int r = 0; r < 4; r++) acc[i][j][r] = 0.f;

    for (int t = 0; t < ntiles; t++) {
        const int s = t % 3;
        CP_WAIT(1);
        __syncthreads();
        if (t + 2 < ntiles) issue(t + 2, (t + 2) % 3);

        const float* As = smg + s * A_ST;
        const float* Bs = smg + 3 * A_ST + s * B_ST;

#pragma unroll
        for (int ks = 0; ks < 2; ks++) {
            const int kb = ks * 8;
            uint32_t af[4][4];
#pragma unroll
            for (int i = 0; i < 4; i++) {
                const float* base = &As[(wm + i * 16 + (lane >> 2)) * ALD3 + kb + (lane & 3)];
                af[i][0] = __float_as_uint(base[0]);
                af[i][1] = __float_as_uint(base[8 * ALD3]);
                af[i][2] = __float_as_uint(base[4]);
                af[i][3] = __float_as_uint(base[8 * ALD3 + 4]);
            }
#pragma unroll
            for (int j = 0; j < 4; j++) {
                uint32_t bf[2];
                const float* base = &Bs[(kb + (lane & 3)) * BLD3 + wn + j * 8 + (lane >> 2)];
                bf[0] = __float_as_uint(base[0]);
                bf[1] = __float_as_uint(base[4 * BLD3]);
#pragma unroll
                for (int i = 0; i < 4; i++)
                    mma_tf32(acc[i][j], af[i], bf);
            }
        }
        __syncthreads();
    }

#pragma unroll
    for (int i = 0; i < 4; i++) {
        const int rbase = m0 + wm + i * 16 + (lane >> 2);
#pragma unroll
        for (int h = 0; h < 2; h++) {
            const int row = rbase + h * 8;
            if (row < M) {
#pragma unroll
                for (int j = 0; j < 4; j++) {
                    const int col = n0 + wn + j * 8 + (lane & 3) * 2;
                    float2 r;
                    r.x = acc[i][j][h * 2 + 0] * alpha;
                    r.y = acc[i][j][h * 2 + 1] * alpha;
                    if (HAS_BIAS) { r.x += bias[col]; r.y += bias[col + 1]; }
                    if (ROUND_OUT) { r.x = f2tf(r.x); r.y = f2tf(r.y); }
                    *(float2*)(Cm + (size_t)row * ldc + col) = r;
                }
            }
        }
    }
}

// =============================================================
// CLS attention: 48 blocks (b,h).
// =============================================================
__global__ __launch_bounds__(256)
void cls_attn_kernel(const float* __restrict__ qkv, float* __restrict__ preout)
{
    __shared__ float sim[NN];
    __shared__ float qv[DD];
    __shared__ float red[256];
    __shared__ float accred[4 * DD];

    const int b = blockIdx.x / HH;
    const int h = blockIdx.x % HH;
    const int tid = threadIdx.x;

    if (tid < DD)
        qv[tid] = qkv[(size_t)(b * NN) * N_QKV + h * DD + tid] * SCALE;
    __syncthreads();

    for (int n = tid; n < NN; n += 256) {
        const float* kp = qkv + (size_t)(b * NN + n) * N_QKV + CC + h * DD;
        float d = 0.f;
#pragma unroll
        for (int c4 = 0; c4 < DD / 4; c4++) {
            float4 k4 = *reinterpret_cast<const float4*>(kp + c4 * 4);
            d += qv[c4*4+0]*k4.x + qv[c4*4+1]*k4.y + qv[c4*4+2]*k4.z + qv[c4*4+3]*k4.w;
        }
        sim[n] = d;
    }
    __syncthreads();

    float m = -1e30f;
    for (int n = tid; n < NN; n += 256) m = fmaxf(m, sim[n]);
    red[tid] = m; __syncthreads();
    for (int o = 128; o > 0; o >>= 1) { if (tid < o) red[tid] = fmaxf(red[tid], red[tid+o]); __syncthreads(); }
    const float mx = red[0];
    __syncthreads();

    float s = 0.f;
    for (int n = tid; n < NN; n += 256) { float e = __expf(sim[n] - mx); sim[n] = e; s += e; }
    red[tid] = s; __syncthreads();
    for (int o = 128; o > 0; o >>= 1) { if (tid < o) red[tid] += red[tid+o]; __syncthreads(); }
    const float inv = 1.f / red[0];
    __syncthreads();

    const int g = tid >> 6, dd = tid & 63;
    float a = 0.f;
    for (int n = g; n < NN; n += 4)
        a += sim[n] * qkv[(size_t)(b * NN + n) * N_QKV + 2 * CC + h * DD + dd];
    accred[g * DD + dd] = a;
    __syncthreads();
    if (tid < DD)
        preout[(size_t)(b * NN) * CC + h * DD + tid] =
            f2tf((accred[tid] + accred[DD + tid] + accred[2*DD + tid] + accred[3*DD + tid]) * inv);
}

// =============================================================
// Space attention v12: v11 + (a) phase-3 k-loop trimmed 28->25
// steps (steps 25..27 multiply exact zero pads: Sc cols>=196 are
// zero AND V rows>=196 are zero -> removed terms are +0.0f exactly),
// (b) redundant end-of-iteration barrier removed (next iteration's
// top CP_WAIT+syncthreads orders phase-3 reads vs new Sc writes);
// an end-of-ITEM barrier protects the K/V refill.
// 512 threads, persistent grid 152, quarter work units (1536).
// =============================================================
#define SA_KLD 68
#define SA_QLD 68
#define V_LD   72
#define SC_LD  228
#define SA_KOFF  0
#define SA_VOFF  15232
#define SA_QOFF  31360
#define SA_QBUF  4352
#define SA_SCOFF 40064
#define SA_FLOATS 54656
#define SA_SMEM (SA_FLOATS * 4)          // 218624 B
#define SA_UNITS (4 * FF * BATCH * HH)   // 1536
#define SA_T 512

__global__ __launch_bounds__(SA_T, 1)
void space_attn_kernel(const float* __restrict__ qkv, float* __restrict__ xt,
                       float* __restrict__ xd)
{
    extern __shared__ float sm[];
    float* Ksm = sm + SA_KOFF;
    float* Vsm = sm + SA_VOFF;
    float* Qb  = sm + SA_QOFF;
    float* Sc  = sm + SA_SCOFF;

    const int tid = threadIdx.x;
    const int w = tid >> 5, lane = tid & 31;
    const uint32_t smbase = smem_u32(sm);

    // one-time zeroing: K pad rows, V pad rows (196..223), Sc pad cols (196..227)
    for (int i = tid; i < 28 * 17; i += SA_T) {
        int r = 196 + i / 17, c = i % 17;
        *reinterpret_cast<float4*>(&Ksm[r * SA_KLD + c * 4]) = make_float4(0.f,0.f,0.f,0.f);
    }
    for (int i = tid; i < 28 * 18; i += SA_T) {
        int r = 196 + i / 18, c = i % 18;
        *reinterpret_cast<float4*>(&Vsm[r * V_LD + c * 4]) = make_float4(0.f,0.f,0.f,0.f);
    }
    for (int i = tid; i < 64 * 32; i += SA_T) {
        int rr = i >> 5, p = 196 + (i & 31);
        Sc[rr * SC_LD + p] = 0.f;
    }
    __syncthreads();

    for (int unit = blockIdx.x; unit < SA_UNITS; unit += gridDim.x) {
        const int rest = unit >> 2;
        const int quarter = ((unit & 3) + rest) & 3;   // rotated: bijective per rest
        const int f  = rest & 7;
        const int bh = rest >> 3;
        const int b  = bh / HH, h = bh % HH;
        const int qt0    = quarter * 6 + (quarter > 0 ? 1 : 0);
        const int niters = (quarter == 0) ? 7 : 6;

        // K/V fill (rows < 196; pads persist as zero). K pre-scaled by SCALE.
        for (int i = tid; i < 196 * 16; i += SA_T) {
            int r = i >> 4, c4 = i & 15;
            size_t base = (size_t)(b * NN + 1 + f * PP + r) * N_QKV + h * DD + c4 * 4;
            float4 kv = *reinterpret_cast<const float4*>(qkv + base + CC);
            kv.x *= SCALE; kv.y *= SCALE; kv.z *= SCALE; kv.w *= SCALE;
            *reinterpret_cast<float4*>(&Ksm[r * SA_KLD + c4 * 4]) = kv;
            *reinterpret_cast<float4*>(&Vsm[r * V_LD + c4 * 4]) =
                *reinterpret_cast<const float4*>(qkv + base + 2 * CC);
        }

        auto issue_q = [&](int it, int buf) {
            const int q0 = (qt0 + it) * 64;
#pragma unroll
            for (int k = 0; k < 2; k++) {
                int i = tid + k * SA_T;
                int r = i >> 4, c4 = i & 15;
                int sq = q0 + r;
                int valid = (sq < SS);
                int sqc = valid ? sq : (SS - 1);
                const float* gp = qkv + (size_t)(b * NN + 1 + sqc) * N_QKV + h * DD + c4 * 4;
                uint32_t sa = smbase + (SA_QOFF + buf * SA_QBUF + r * SA_QLD + c4 * 4) * 4;
                cp_async16(sa, gp, valid ? 16 : 0);
            }
            CP_COMMIT();
        };

        issue_q(0, 0);

        for (int it = 0; it < niters; it++) {
            const int buf = it & 1;
            const int q0 = (qt0 + it) * 64;
            const float* Qsm = Qb + buf * SA_QBUF;

            CP_WAIT(0);
            __syncthreads();     // Q + K/V visible; prev phase-3 done

            if (it + 1 < niters) issue_q(it + 1, buf ^ 1);

            // ---- phase 1: S[64][224] = Q @ (K*SCALE)^T; warp tile 16m x 56n ----
            const int mrow1  = (w >> 2) * 16;
            const int nbase1 = (w & 3) * 56;
            float acc[7][4];
#pragma unroll
            for (int nt = 0; nt < 7; nt++)
#pragma unroll
                for (int r = 0; r < 4; r++) acc[nt][r] = 0.f;

            {
                uint32_t aA[2][4], bB[2][7][2];
                auto ldfrag1 = [&](int kb, int pb) {
                    const float* ab = &Qsm[(mrow1 + (lane >> 2)) * SA_QLD + kb + (lane & 3)];
                    aA[pb][0] = __float_as_uint(ab[0]);
                    aA[pb][1] = __float_as_uint(ab[8 * SA_QLD]);
                    aA[pb][2] = __float_as_uint(ab[4]);
                    aA[pb][3] = __float_as_uint(ab[8 * SA_QLD + 4]);
#pragma unroll
                    for (int nt = 0; nt < 7; nt++) {
                        const float* bb = &Ksm[(nbase1 + nt * 8 + (lane >> 2)) * SA_KLD + kb + (lane & 3)];
                        bB[pb][nt][0] = __float_as_uint(bb[0]);
                        bB[pb][nt][1] = __float_as_uint(bb[4]);
                    }
                };
                ldfrag1(0, 0);
#pragma unroll
                for (int kk = 0; kk < 8; kk++) {
                    const int pb = kk & 1;
                    if (kk < 7) ldfrag1((kk + 1) * 8, pb ^ 1);
#pragma unroll
                    for (int nt = 0; nt < 7; nt++)
                        mma_tf32(acc[nt], aA[pb], bB[pb][nt]);
                }
            }

            // store scores (already scaled via K); float2 stores, cols<196
            {
                const int r0 = mrow1 + (lane >> 2);
#pragma unroll
                for (int nt = 0; nt < 7; nt++) {
                    int col = nbase1 + nt * 8 + (lane & 3) * 2;
                    if (col < 196) {
                        *reinterpret_cast<float2*>(&Sc[r0 * SC_LD + col]) =
                            make_float2(acc[nt][0], acc[nt][1]);
                        *reinterpret_cast<float2*>(&Sc[(r0 + 8) * SC_LD + col]) =
                            make_float2(acc[nt][2], acc[nt][3]);
                    }
                }
            }
            __syncthreads();

            // ---- phase 2: softmax over p; 4 rows per warp ----
#pragma unroll
            for (int qi = 0; qi < 4; qi++) {
                const int q = w * 4 + qi;
                float v[7];
                float mx = -1e30f;
#pragma unroll
                for (int j = 0; j < 7; j++) {
                    int p = lane + 32 * j;
                    v[j] = (p < 196) ? Sc[q * SC_LD + p] : -1e30f;
                    mx = fmaxf(mx, v[j]);
                }
#pragma unroll
                for (int o = 16; o > 0; o >>= 1) mx = fmaxf(mx, __shfl_xor_sync(0xffffffffu, mx, o));
                float sum = 0.f;
#pragma unroll
                for (int j = 0; j < 7; j++) {
                    int p = lane + 32 * j;
                    float e = (p < 196) ? __expf(v[j] - mx) : 0.f;
                    v[j] = e; sum += e;
                }
#pragma unroll
                for (int o = 16; o > 0; o >>= 1) sum += __shfl_xor_sync(0xffffffffu, sum, o);
                float inv = 1.f / sum;
#pragma unroll
                for (int j = 0; j < 7; j++) {
                    int p = lane + 32 * j;
                    if (p < 196) Sc[q * SC_LD + p] = f2tf(v[j] * inv);
                }
            }
            __syncthreads();

            // ---- phase 3: out[64][64] = Sc @ V; warp tile 16m x 16n ----
            // k-loop trimmed to 25 steps (p in [0,200)): steps 25..27 are
            // exact-zero pad work (Sc cols>=196 == 0 AND V rows>=196 == 0).
            {
                const int m3  = (w >> 2) * 16;
                const int nb3 = (w & 3) * 16;
                float o2[2][4];
#pragma unroll
                for (int j = 0; j < 2; j++)
#pragma unroll
                    for (int r = 0; r < 4; r++) o2[j][r] = 0.f;

                uint32_t a3[2][4], b3[2][2][2];
                auto ldfrag3 = [&](int kb, int pb) {
                    const float* ab = &Sc[(m3 + (lane >> 2)) * SC_LD + kb + (lane & 3)];
                    a3[pb][0] = __float_as_uint(ab[0]);
                    a3[pb][1] = __float_as_uint(ab[8 * SC_LD]);
                    a3[pb][2] = __float_as_uint(ab[4]);
                    a3[pb][3] = __float_as_uint(ab[8 * SC_LD + 4]);
#pragma unroll
                    for (int j = 0; j < 2; j++) {
                        const float* bb = &Vsm[(kb + (lane & 3)) * V_LD + nb3 + j * 8 + (lane >> 2)];
                        b3[pb][j][0] = __float_as_uint(bb[0]);
                        b3[pb][j][1] = __float_as_uint(bb[4 * V_LD]);
                    }
                };
                ldfrag3(0, 0);
#pragma unroll
                for (int kk = 0; kk < 25; kk++) {
                    const int pb = kk & 1;
                    if (kk < 24) ldfrag3((kk + 1) * 8, pb ^ 1);
                    mma_tf32(o2[0], a3[pb], b3[pb][0]);
                    mma_tf32(o2[1], a3[pb], b3[pb][1]);
                }

                const int r0 = m3 + (lane >> 2);
#pragma unroll
                for (int hh2 = 0; hh2 < 2; hh2++) {
                    const int sq = q0 + r0 + hh2 * 8;
                    if (sq < SS) {
                        float* xp = xt + ((size_t)(b * SS + sq) * FF + f) * CC + h * DD;
                        const bool diag = (sq / PP == f);
                        float* dp = xd + (size_t)(b * SS + sq) * CC + h * DD;
#pragma unroll
                        for (int j = 0; j < 2; j++) {
                            const int dv = nb3 + j * 8 + (lane & 3) * 2;
                            float2 r;
                            r.x = o2[j][hh2 * 2 + 0];
                            r.y = o2[j][hh2 * 2 + 1];
                            *reinterpret_cast<float2*>(xp + dv) = r;
                            if (diag) {
                                float2 rr = make_float2(f2tf(r.x), f2tf(r.y));
                                *reinterpret_cast<float2*>(dp + dv) = rr;
                            }
                        }
                    }
                }
            }
            // no end-of-iteration barrier: next iteration's top
            // CP_WAIT + __syncthreads orders phase-3 reads before
            // any new Sc writes (score-store comes after that barrier)
        }
        __syncthreads();   // end of item: protect K/V refill vs this phase-3
    }
}

// =============================================================
// gemm_G tf32: per head h, G[m,c] = sum_k q2[m,h64+k]*wkv[c,h64+k]
// =============================================================
__global__ __launch_bounds__(256)
void gemm_G_tf32(const float* __restrict__ q2, const float* __restrict__ wkv,
                 float* __restrict__ G)
{
    __shared__ float As[128 * 68];
    __shared__ float Bs[128 * 68];

    const int mt = blockIdx.x, ct = blockIdx.y, h = blockIdx.z;
    const int tid = threadIdx.x;
    const int lane = tid & 31;
    const int w = tid >> 5;

    for (int i = tid; i < 128 * 16; i += 256) {
        int r = i >> 4, c4 = i & 15;
        *reinterpret_cast<float4*>(&As[r * 68 + 4 * c4]) =
            *reinterpret_cast<const float4*>(q2 + (size_t)(mt * 128 + r) * CC + h * DD + 4 * c4);
        *reinterpret_cast<float4*>(&Bs[r * 68 + 4 * c4]) =
            *reinterpret_cast<const float4*>(wkv + (size_t)(ct * 128 + r) * (2 * CC) + h * DD + 4 * c4);
    }
    __syncthreads();

    const int wm = (w >> 2) * 64;
    const int wn = (w & 3) * 32;

    float acc[4][4][4];
#pragma unroll
    for (int i = 0; i < 4; i++)
#pragma unroll
        for (int j = 0; j < 4; j++)
#pragma unroll
            for (int r = 0; r < 4; r++) acc[i][j][r] = 0.f;

#pragma unroll
    for (int kb = 0; kb < 64; kb += 8) {
        uint32_t af[4][4], bf[4][2];
#pragma unroll
        for (int i = 0; i < 4; i++) {
            const float* base = &As[(wm + i * 16 + (lane >> 2)) * 68 + kb + (lane & 3)];
            af[i][0] = __float_as_uint(base[0]);
            af[i][1] = __float_as_uint(base[8 * 68]);
            af[i][2] = __float_as_uint(base[4]);
            af[i][3] = __float_as_uint(base[8 * 68 + 4]);
        }
#pragma unroll
        for (int j = 0; j < 4; j++) {
            const float* base = &Bs[(wn + j * 8 + (lane >> 2)) * 68 + kb + (lane & 3)];
            bf[j][0] = __float_as_uint(base[0]);
            bf[j][1] = __float_as_uint(base[4]);
        }
#pragma unroll
        for (int i = 0; i < 4; i++)
#pragma unroll
            for (int j = 0; j < 4; j++)
                mma_tf32(acc[i][j], af[i], bf[j]);
    }

#pragma unroll
    for (int i = 0; i < 4; i++) {
        const int rbase = mt * 128 + wm + i * 16 + (lane >> 2);
#pragma unroll
        for (int hh2 = 0; hh2 < 2; hh2++) {
            const size_t row = rbase + hh2 * 8;
            float* gp = G + (row * HH + h) * CC + ct * 128;
#pragma unroll
            for (int j = 0; j < 4; j++) {
                const int col = wn + j * 8 + (lane & 3) * 2;
                float2 r;
                r.x = acc[i][j][hh2 * 2 + 0];
                r.y = acc[i][j][hh2 * 2 + 1];
                *reinterpret_cast<float2*>(gp + col) = r;
            }
        }
    }
}

// =============================================================
// score_out v2: per (b,s). G in registers (warp-per-head), xt in smem.
// =============================================================
#define SO_SMEM ((FF*CC + 96 + 96) * 4)

__global__ __launch_bounds__(256)
void score_out_kernel(const float* __restrict__ xt, const float* __restrict__ G,
                      float* __restrict__ preout, float* __restrict__ attn2)
{
    extern __shared__ float sm[];
    float* xts = sm;
    float* sc  = xts + FF * CC;
    float* pr  = sc + 96;

    const int bs = blockIdx.x;
    const int b = bs / SS, s = bs % SS;
    const int tid = threadIdx.x;
    const int w = tid >> 5, l = tid & 31;

    for (int i = tid; i < FF * CC / 4; i += 256)
        reinterpret_cast<float4*>(xts)[i] =
            reinterpret_cast<const float4*>(xt)[(size_t)bs * (FF * CC / 4) + i];
    __syncthreads();

    for (int h = w; h < HH; h += 8) {
        const float4* gp = reinterpret_cast<const float4*>(G + ((size_t)bs * HH + h) * CC);
        float4 g[6];
#pragma unroll
        for (int j = 0; j < 6; j++) g[j] = gp[l + 32 * j];
#pragma unroll
        for (int f = 0; f < FF; f++) {
            const float4* xp = reinterpret_cast<const float4*>(xts + f * CC);
            float part = 0.f;
#pragma unroll
            for (int j = 0; j < 6; j++) {
                float4 x4 = xp[l + 32 * j];
                part += g[j].x*x4.x + g[j].y*x4.y + g[j].z*x4.z + g[j].w*x4.w;
            }
#pragma unroll
            for (int o = 16; o > 0; o >>= 1) part += __shfl_xor_sync(0xffffffffu, part, o);
            if (l == 0) sc[h * 8 + f] = part;
        }
    }
    __syncthreads();

    if (tid < HH) {
        int h = tid;
        float mx = -1e30f;
#pragma unroll
        for (int f = 0; f < FF; f++) mx = fmaxf(mx, sc[h * 8 + f]);
        float sum = 0.f;
        float e[FF];
#pragma unroll
        for (int f = 0; f < FF; f++) { e[f] = __expf(sc[h * 8 + f] - mx); sum += e[f]; }
        float inv = 1.f / sum;
#pragma unroll
        for (int f = 0; f < FF; f++) {
            float p = e[f] * inv;
            pr[h * 8 + f] = p;
            attn2[((size_t)(b * HH + h) * SS + s) * FF + f] = p;
        }
    }
    __syncthreads();

    for (int c = tid; c < CC; c += 256) {
        int h = c >> 6;
        float v = 0.f;
#pragma unroll
        for (int f = 0; f < FF; f++) v += pr[h * 8 + f] * xts[f * CC + c];
        preout[(size_t)(b * NN + 1 + s) * CC + c] = f2tf(v);
    }
}

// =============================================================
// host launch
// =============================================================
extern "C" void kernel_launch(void* const* d_in, const int* in_sizes, int n_in,
                              void* d_out, int out_size)
{
    const float* x      = (const float*)d_in[0];
    const float* w_qkv  = (const float*)d_in[1];
    const float* w_q    = (const float*)d_in[2];
    const float* w_kv   = (const float*)d_in[3];
    const float* w_proj = (const float*)d_in[4];
    const float* b_proj = (const float*)d_in[5];

    float *p_qkv, *p_xt, *p_xd, *p_q2, *p_G, *p_pre;
    float *p_xr, *p_wqkvr, *p_wqr, *p_wkvr, *p_wprojr;
    cudaGetSymbolAddress((void**)&p_qkv, g_qkv);
    cudaGetSymbolAddress((void**)&p_xt,  g_xt);
    cudaGetSymbolAddress((void**)&p_xd,  g_xd);
    cudaGetSymbolAddress((void**)&p_q2,  g_q2);
    cudaGetSymbolAddress((void**)&p_G,   g_G);
    cudaGetSymbolAddress((void**)&p_pre, g_pre);
    cudaGetSymbolAddress((void**)&p_xr,     g_xr);
    cudaGetSymbolAddress((void**)&p_wqkvr,  g_wqkvr);
    cudaGetSymbolAddress((void**)&p_wqr,    g_wqr);
    cudaGetSymbolAddress((void**)&p_wkvr,   g_wkvr);
    cudaGetSymbolAddress((void**)&p_wprojr, g_wprojr);

    cudaFuncSetAttribute((const void*)gemm_tf32<false, true>,  cudaFuncAttributeMaxDynamicSharedMemorySize, GT_SMEM);
    cudaFuncSetAttribute((const void*)gemm_tf32<true,  false>, cudaFuncAttributeMaxDynamicSharedMemorySize, GT_SMEM);
    cudaFuncSetAttribute(space_attn_kernel, cudaFuncAttributeMaxDynamicSharedMemorySize, SA_SMEM);
    cudaFuncSetAttribute(score_out_kernel,  cudaFuncAttributeMaxDynamicSharedMemorySize, SO_SMEM);

    float* outp  = (float*)d_out;
    float* attn2 = outp + OUT_ELEMS;

    // 0) tf32-round all GEMM inputs in one launch
    round_all<<<(RC_TOTAL + 255) / 256, 256>>>(
        x, p_xr, w_qkv, p_wqkvr, w_q, p_wqr, w_kv, p_wkvr, w_proj, p_wprojr);

    // 1) qkv = x @ w_qkv (tf32, output rounded)
    gemm_tf32<false, true><<<dim3(N_QKV/128, (M_QKV+127)/128), 256, GT_SMEM>>>(
        p_xr, p_wqkvr, p_qkv, nullptr, M_QKV, N_QKV, CC, CC, N_QKV, N_QKV, 1.f);

    // 2) cls attention -> preout row n=0 (rounded)
    cls_attn_kernel<<<BATCH*HH, 256>>>(p_qkv, p_pre);

    // 3) fused space attention (trimmed PV + fewer barriers) -> xt, xd(rounded)
    space_attn_kernel<<<152, SA_T, SA_SMEM>>>(p_qkv, p_xt, p_xd);

    // 4) q2 = scale * x_diag @ w_q (tf32, output rounded)
    gemm_tf32<false, true><<<dim3(CC/128, M_S/128), 256, GT_SMEM>>>(
        p_xd, p_wqr, p_q2, nullptr, M_S, CC, CC, CC, CC, CC, SCALE);

    // 5) G = per-head q2 @ Wk_h^T
    gemm_G_tf32<<<dim3(M_S/128, CC/128, HH), 256>>>(p_q2, p_wkvr, p_G);

    // 6) scores + softmax(F) -> attn2; weighted xt -> preout (rounded)
    score_out_kernel<<<M_S, 256, SO_SMEM>>>(p_xt, p_G, p_pre, attn2);

    // 7) out = preout @ w_proj + b_proj (full-precision output)
    gemm_tf32<true, false><<<dim3(CC/128, (M_QKV+127)/128), 256, GT_SMEM>>>(
        p_pre, p_wprojr, outp, b_proj, M_QKV, CC, CC, CC, CC, CC, 1.f);
}